// round 3
// baseline (speedup 1.0000x reference)
#include <cuda_runtime.h>
#include <math.h>

// Problem constants
#define Bq 64          // batch (M)
#define Hd 1024        // hidden
#define Tt 128         // seq len
#define NSTEP 127      // timesteps executed (cols 1..127)
#define Cc 50000       // num classes
#define NT 32          // N tile
#define KC 32          // K chunk in smem
#define ASTRIDE 68     // smem A row stride (floats)
#define WSTRIDE 36     // smem W row stride

// Scratch (no cudaMalloc allowed)
__device__ float g_h[2][Bq * Hd];
__device__ float g_out1[Bq * Hd];
__device__ float g_out23[Bq * 2 * Hd];
__device__ float g_out45[Bq * 2 * Hd];
__device__ float g_part[256 * Bq * NT];   // split-K partials: up to 256 (split,tile) slots of 64x32
__device__ unsigned g_ctr[24576];         // per-launch-tile arrival counters (reset after use)
__device__ float g_c[3];                  // softmax leaf-combine coefficients

struct GArgs {
    const float* A; int lda;
    const float* W;        // primary weight rows [*, 1024]
    const float* W2;       // phase-1 second half weight (W0)
    const float* bias;     // length Nlim
    const float* bias2;    // phase-1 extra bias (b0), else null
    const float* wv;       // word2vec (phase 1 only; also flags phase-1 mode)
    const int*   idx;      // token id column (batch_input + t + 1)
    int idx_stride;        // = Tt
    int nsplit; int ntiles; int Nlim; int klen;
    unsigned* ctr;
    float* out; int ldo;
    int mode;              // 0 tanh | 1 relu/sigmoid | 2 tanh/relu | 3 combine | 4 none
    const float* e1; const float* e2;  // combine inputs (out23, out45)
};

__device__ __forceinline__ float epilogue_fn(const GArgs& g, float v, int m, int ng) {
    v += g.bias[ng];
    if (g.bias2) v += g.bias2[ng];
    switch (g.mode) {
        case 0: return tanhf(v);
        case 1: return (ng < Hd) ? fmaxf(v, 0.f) : (1.f / (1.f + expf(-v)));
        case 2: return (ng < Hd) ? tanhf(v) : fmaxf(v, 0.f);
        case 3: return g_c[2] * tanhf(v)
                     + g_c[0] * g.e1[(size_t)m * 2 * Hd + ng]
                     + g_c[1] * g.e2[(size_t)m * 2 * Hd + ng];
        default: return v;
    }
}

// C[64, NT] (+= over split-K) = A[64, K] @ W[NT, K]^T, tiled; last split CTA applies epilogue.
__global__ void __launch_bounds__(128) gemm_tile(GArgs g) {
    __shared__ __align__(16) float As[KC][ASTRIDE];
    __shared__ __align__(16) float Wsh[KC][WSTRIDE];
    __shared__ int lastFlag;

    const int tile = blockIdx.x;
    const int s    = blockIdx.y;
    const int tid  = threadIdx.x;
    const int n0   = tile * NT;

    // Select K segment source
    const bool ph1 = (g.wv != nullptr);
    const float* Wp = g.W;
    int kbase;
    bool gather = false;
    if (ph1) {
        if (s < 4) { kbase = s * 256; }
        else       { Wp = g.W2; kbase = (s - 4) * 256; gather = true; }
    } else {
        kbase = s * g.klen;
    }

    // Warp-friendly thread mapping: 8 lanes broadcast A frag, 4 lanes broadcast W frag
    const int w    = tid >> 5;            // warp 0..3 -> m block of 16
    const int lane = tid & 31;
    const int midx = lane >> 3;           // 0..3
    const int nidx = lane & 7;            // 0..7
    const int mt   = w * 16 + midx * 4;   // 0..60
    const int nt   = nidx * 4;            // 0..28

    float acc[4][4] = {};

    for (int kc = 0; kc < g.klen; kc += KC) {
        const int kg = kbase + kc;
        // Load A chunk [64 x 32] -> transposed As[k][m]
        #pragma unroll
        for (int i = 0; i < 4; i++) {
            int q  = tid + 128 * i;       // 0..511 float4 slots
            int m  = q >> 3;
            int kk = (q & 7) << 2;
            const float* ar = gather
                ? g.wv + (size_t)__ldg(g.idx + m * g.idx_stride) * Hd
                : g.A  + (size_t)m * g.lda;
            float4 v = *(const float4*)(ar + kg + kk);
            As[kk + 0][m] = v.x; As[kk + 1][m] = v.y;
            As[kk + 2][m] = v.z; As[kk + 3][m] = v.w;
        }
        // Load W chunk [32 n x 32 k] -> transposed Wsh[k][n]
        #pragma unroll
        for (int i = 0; i < 2; i++) {
            int q  = tid + 128 * i;       // 0..255
            int n  = q >> 3;
            int kk = (q & 7) << 2;
            int ng = n0 + n;
            float4 v = make_float4(0.f, 0.f, 0.f, 0.f);
            if (ng < g.Nlim) v = *(const float4*)(Wp + (size_t)ng * Hd + kg + kk);
            Wsh[kk + 0][n] = v.x; Wsh[kk + 1][n] = v.y;
            Wsh[kk + 2][n] = v.z; Wsh[kk + 3][n] = v.w;
        }
        __syncthreads();
        #pragma unroll
        for (int k = 0; k < KC; k++) {
            float4 av = *(const float4*)&As[k][mt];
            float4 wv4 = *(const float4*)&Wsh[k][nt];
            acc[0][0] += av.x * wv4.x; acc[0][1] += av.x * wv4.y;
            acc[0][2] += av.x * wv4.z; acc[0][3] += av.x * wv4.w;
            acc[1][0] += av.y * wv4.x; acc[1][1] += av.y * wv4.y;
            acc[1][2] += av.y * wv4.z; acc[1][3] += av.y * wv4.w;
            acc[2][0] += av.z * wv4.x; acc[2][1] += av.z * wv4.y;
            acc[2][2] += av.z * wv4.z; acc[2][3] += av.z * wv4.w;
            acc[3][0] += av.w * wv4.x; acc[3][1] += av.w * wv4.y;
            acc[3][2] += av.w * wv4.z; acc[3][3] += av.w * wv4.w;
        }
        __syncthreads();
    }

    if (g.nsplit == 1) {
        #pragma unroll
        for (int i = 0; i < 4; i++)
            #pragma unroll
            for (int j = 0; j < 4; j++) {
                int ng = n0 + nt + j;
                if (ng < g.Nlim)
                    g.out[(size_t)(mt + i) * g.ldo + ng] = epilogue_fn(g, acc[i][j], mt + i, ng);
            }
        return;
    }

    // Split-K: write partials, last-arriving CTA reduces + runs epilogue
    float* p = &g_part[(size_t)(s * g.ntiles + tile) * (Bq * NT)];
    #pragma unroll
    for (int i = 0; i < 4; i++)
        #pragma unroll
        for (int j = 0; j < 4; j++)
            p[(mt + i) * NT + (nt + j)] = acc[i][j];
    __threadfence();
    __syncthreads();
    if (tid == 0) {
        unsigned prev = atomicAdd(&g.ctr[tile], 1u);
        lastFlag = (prev == (unsigned)(g.nsplit - 1));
    }
    __syncthreads();
    if (!lastFlag) return;
    __threadfence();
    #pragma unroll
    for (int i = 0; i < 4; i++)
        #pragma unroll
        for (int j = 0; j < 4; j++) {
            float v = 0.f;
            for (int ss = 0; ss < g.nsplit; ss++)
                v += __ldcg(&g_part[(size_t)(ss * g.ntiles + tile) * (Bq * NT)
                                    + (mt + i) * NT + (nt + j)]);
            int ng = n0 + nt + j;
            g.out[(size_t)(mt + i) * g.ldo + ng] = epilogue_fn(g, v, mt + i, ng);
        }
    __threadfence();
    if (tid == 0) g.ctr[tile] = 0;  // reset for next graph replay
}

__global__ void coef_kernel(const float* __restrict__ Wsum, const float* __restrict__ bsum,
                            const float* __restrict__ actions) {
    if (threadIdx.x == 0) {
        const int rows[3] = {1, 3, 5};  // leaves 2,4,6 -> weight idx l-1
        float wgt[3];
        for (int i = 0; i < 3; i++) {
            float acc = bsum[rows[i]];
            for (int j = 0; j < 12; j++) acc += Wsum[rows[i] * 12 + j] * actions[j];
            wgt[i] = acc;
        }
        float mx = fmaxf(wgt[0], fmaxf(wgt[1], wgt[2]));
        float e0 = expf(wgt[0] - mx), e1 = expf(wgt[1] - mx), e2 = expf(wgt[2] - mx);
        float ssum = e0 + e1 + e2;
        g_c[0] = e0 / ssum; g_c[1] = e1 / ssum; g_c[2] = e2 / ssum;
    }
}

__global__ void copy_h_kernel(const float* __restrict__ h) {
    int i = blockIdx.x * blockDim.x + threadIdx.x;
    if (i < Bq * Hd) g_h[0][i] = h[i];
}

extern "C" void kernel_launch(void* const* d_in, const int* in_sizes, int n_in,
                              void* d_out, int out_size) {
    (void)in_sizes; (void)n_in; (void)out_size;
    const float* wv      = (const float*)d_in[0];
    const float* h       = (const float*)d_in[1];
    const int*   bi      = (const int*)  d_in[2];
    const float* W0      = (const float*)d_in[3];
    const float* b0      = (const float*)d_in[4];
    const float* Ws      = (const float*)d_in[5];
    const float* bs      = (const float*)d_in[6];
    const float* W_out   = (const float*)d_in[7];
    const float* b_out   = (const float*)d_in[8];
    const float* W_sum   = (const float*)d_in[9];
    const float* b_sum   = (const float*)d_in[10];
    const float* actions = (const float*)d_in[11];

    float *gh, *go1, *go23, *go45;
    unsigned* gctr;
    cudaGetSymbolAddress((void**)&gh,   g_h);
    cudaGetSymbolAddress((void**)&go1,  g_out1);
    cudaGetSymbolAddress((void**)&go23, g_out23);
    cudaGetSymbolAddress((void**)&go45, g_out45);
    cudaGetSymbolAddress((void**)&gctr, g_ctr);

    coef_kernel<<<1, 32>>>(W_sum, b_sum, actions);
    copy_h_kernel<<<(Bq * Hd + 255) / 256, 256>>>(h);

    unsigned ofs = 0;
    for (int t = 0; t < NSTEP; t++) {
        const float* hin  = gh + (size_t)(t & 1) * Bq * Hd;
        float*       hout = gh + (size_t)((t + 1) & 1) * Bq * Hd;

        {   // phase 1: out1 = tanh(h @ Ws0^T + wv[idx] @ W0^T + bs0 + b0)   (virtual K=2048)
            GArgs a = {};
            a.A = hin; a.lda = Hd; a.W = Ws; a.W2 = W0; a.bias = bs; a.bias2 = b0;
            a.wv = wv; a.idx = bi + (t + 1); a.idx_stride = Tt;
            a.nsplit = 8; a.ntiles = 32; a.Nlim = Hd; a.klen = 256;
            a.ctr = gctr + ofs; ofs += 32;
            a.out = go1; a.ldo = Hd; a.mode = 0;
            gemm_tile<<<dim3(32, 8), 128>>>(a);
        }
        {   // phase 2: [out2 | out3] = [relu | sigmoid](out1 @ [Ws1;Ws2]^T + [bs1;bs2])
            GArgs a = {};
            a.A = go1; a.lda = Hd; a.W = Ws + (size_t)Hd * Hd; a.bias = bs + Hd;
            a.nsplit = 4; a.ntiles = 64; a.Nlim = 2 * Hd; a.klen = 256;
            a.ctr = gctr + ofs; ofs += 64;
            a.out = go23; a.ldo = 2 * Hd; a.mode = 1;
            gemm_tile<<<dim3(64, 4), 128>>>(a);
        }
        {   // phase 3: [out4 | out5] = [tanh | relu](out3 @ [Ws3;Ws4]^T + [bs3;bs4])
            GArgs a = {};
            a.A = go23 + Hd; a.lda = 2 * Hd; a.W = Ws + (size_t)3 * Hd * Hd; a.bias = bs + 3 * Hd;
            a.nsplit = 4; a.ntiles = 64; a.Nlim = 2 * Hd; a.klen = 256;
            a.ctr = gctr + ofs; ofs += 64;
            a.out = go45; a.ldo = 2 * Hd; a.mode = 2;
            gemm_tile<<<dim3(64, 4), 128>>>(a);
        }
        {   // phase 4: h_new = c2*tanh(out5 @ Ws5^T + bs5) + c0*out2 + c1*out4
            GArgs a = {};
            a.A = go45 + Hd; a.lda = 2 * Hd; a.W = Ws + (size_t)5 * Hd * Hd; a.bias = bs + 5 * Hd;
            a.nsplit = 4; a.ntiles = 32; a.Nlim = Hd; a.klen = 256;
            a.ctr = gctr + ofs; ofs += 32;
            a.out = hout; a.ldo = Hd; a.mode = 3;
            a.e1 = go23; a.e2 = go45;
            gemm_tile<<<dim3(32, 4), 128>>>(a);
        }
    }

    {   // final: logits = h_final @ W_out^T + b_out   [64, 50000]
        GArgs a = {};
        a.A = gh + (size_t)(NSTEP & 1) * Bq * Hd; a.lda = Hd;
        a.W = W_out; a.bias = b_out;
        a.nsplit = 1; a.ntiles = 0; a.Nlim = Cc; a.klen = Hd;
        a.out = (float*)d_out; a.ldo = Cc; a.mode = 4;
        gemm_tile<<<dim3((Cc + NT - 1) / NT, 1), 128>>>(a);
    }
}

// round 6
// speedup vs baseline: 1.8113x; 1.8113x over previous
#include <cuda_runtime.h>
#include <math.h>

#define Bq 64
#define Hd 1024
#define Tt 128
#define NSTEP 127
#define Cc 50000

#define TM 64
#define TN 64
#define KCH 32
#define AST 36     // A smem row stride (floats), float4-aligned
#define WST 34     // W smem row stride (floats), float2-aligned, conflict-free reads

// Scratch (no cudaMalloc allowed)
__device__ float g_h[2][Bq * Hd];
__device__ float g_out1[Bq * Hd];
__device__ float g_out23[Bq * 2 * Hd];
__device__ float g_out45[Bq * 2 * Hd];
__device__ float g_part[256 * 4096];      // up to 256 (tile,split) slots of 64x64
__device__ unsigned g_ctr[16384];          // per-launch-tile arrival counters (reset after use)
__device__ float g_c[3];                   // softmax leaf-combine coefficients

struct GArgs {
    const float* A; int lda;
    const float* W;        // weight rows [*, 1024]
    const float* W2;       // phase-1 second weight (W0)
    const float* bias;
    const float* bias2;    // phase-1 extra bias (b0)
    const float* wv;       // word2vec (phase-1 flag)
    const int*   idx;      // token column base
    int nsplit; int split1; int Nlim; int kper;
    unsigned* ctr;
    float* out; int ldo;
    int mode;              // 0 tanh | 1 relu/sigmoid | 2 tanh/relu | 3 combine | 4 none
    const float* e1; const float* e2;
};

__device__ __forceinline__ unsigned long long ffma2(unsigned long long a,
                                                    unsigned long long b,
                                                    unsigned long long c) {
    unsigned long long d;
    asm("fma.rn.f32x2 %0, %1, %2, %3;" : "=l"(d) : "l"(a), "l"(b), "l"(c));
    return d;
}

__device__ __forceinline__ float unpack_sum(unsigned long long p) {
    float lo, hi;
    asm("mov.b64 {%0, %1}, %2;" : "=f"(lo), "=f"(hi) : "l"(p));
    return lo + hi;
}

__device__ __forceinline__ float epilogue_fn(const GArgs& g, float v, int m, int ng) {
    v += g.bias[ng];
    if (g.bias2) v += g.bias2[ng];
    switch (g.mode) {
        case 0: return tanhf(v);
        case 1: return (ng < Hd) ? fmaxf(v, 0.f) : (1.f / (1.f + expf(-v)));
        case 2: return (ng < Hd) ? tanhf(v) : fmaxf(v, 0.f);
        case 3: return g_c[2] * tanhf(v)
                     + g_c[0] * g.e1[(size_t)m * 2 * Hd + ng]
                     + g_c[1] * g.e2[(size_t)m * 2 * Hd + ng];
        default: return v;
    }
}

// C[64, 64] = A[64, kper] @ W[64, kper]^T (one K-split slice).
// Last-arriving split CTA reduces partials with all 256 threads and runs the epilogue.
__global__ void __launch_bounds__(256, 2) gemm_tile(GArgs g) {
    __shared__ __align__(16) float As[2][TM][AST];
    __shared__ __align__(16) float Wsm[2][TN][WST];
    __shared__ int lastFlag;

    const int tile = blockIdx.x;
    const int s    = blockIdx.y;
    const int tid  = threadIdx.x;
    const int n0   = tile * TN;

    // K-segment source selection (phase 1 fuses two GEMMs over virtual K=2048)
    const float* Wp = g.W;
    bool gather = false;
    int kbase;
    if (g.wv && s >= g.split1) { Wp = g.W2; gather = true; kbase = (s - g.split1) * g.kper; }
    else                       { kbase = s * g.kper; }

    // Global load row pointers (2 A rows + 2 W rows per thread per chunk)
    const int mr0 = tid >> 3, mr1 = mr0 + 32;
    const int kf  = (tid & 7) * 4;
    const float *arow0, *arow1;
    if (gather) {
        arow0 = g.wv + (size_t)__ldg(g.idx + mr0 * Tt) * Hd;
        arow1 = g.wv + (size_t)__ldg(g.idx + mr1 * Tt) * Hd;
    } else {
        arow0 = g.A + (size_t)mr0 * g.lda;
        arow1 = g.A + (size_t)mr1 * g.lda;
    }
    arow0 += kbase + kf; arow1 += kbase + kf;
    const bool wok0 = (n0 + mr0) < g.Nlim;
    const bool wok1 = (n0 + mr1) < g.Nlim;
    const float* wrow0 = Wp + (size_t)(n0 + mr0) * Hd + kbase + kf;
    const float* wrow1 = Wp + (size_t)(n0 + mr1) * Hd + kbase + kf;

    // Compute-thread mapping: rows mt..mt+3, cols c+16j (interleaved for bank-free W reads)
    const int r  = tid >> 4;
    const int c  = tid & 15;
    const int mt = r * 4;

    unsigned long long acc[4][4];
    #pragma unroll
    for (int i = 0; i < 4; i++)
        #pragma unroll
        for (int j = 0; j < 4; j++) acc[i][j] = 0ull;

    const int nch = g.kper / KCH;
    const float4 z4 = make_float4(0.f, 0.f, 0.f, 0.f);

    // Prologue: load chunk 0
    float4 va0 = *(const float4*)(arow0);
    float4 va1 = *(const float4*)(arow1);
    float4 vw0 = wok0 ? *(const float4*)(wrow0) : z4;
    float4 vw1 = wok1 ? *(const float4*)(wrow1) : z4;
    *(float4*)&As[0][mr0][kf] = va0;
    *(float4*)&As[0][mr1][kf] = va1;
    *(float2*)&Wsm[0][mr0][kf]     = make_float2(vw0.x, vw0.y);
    *(float2*)&Wsm[0][mr0][kf + 2] = make_float2(vw0.z, vw0.w);
    *(float2*)&Wsm[0][mr1][kf]     = make_float2(vw1.x, vw1.y);
    *(float2*)&Wsm[0][mr1][kf + 2] = make_float2(vw1.z, vw1.w);
    __syncthreads();

    for (int ch = 0; ch < nch; ch++) {
        const int b = ch & 1;
        const bool more = (ch + 1) < nch;
        if (more) {
            const int o = (ch + 1) * KCH;
            va0 = *(const float4*)(arow0 + o);
            va1 = *(const float4*)(arow1 + o);
            vw0 = wok0 ? *(const float4*)(wrow0 + o) : z4;
            vw1 = wok1 ? *(const float4*)(wrow1 + o) : z4;
        }
        // Compute on buffer b: 8 k4-rounds
        #pragma unroll
        for (int k4 = 0; k4 < KCH / 4; k4++) {
            ulonglong2 a[4];
            #pragma unroll
            for (int i = 0; i < 4; i++)
                a[i] = *(const ulonglong2*)&As[b][mt + i][k4 * 4];
            #pragma unroll
            for (int j = 0; j < 4; j++) {
                const int n = c + 16 * j;
                unsigned long long wlo = *(const unsigned long long*)&Wsm[b][n][k4 * 4];
                unsigned long long whi = *(const unsigned long long*)&Wsm[b][n][k4 * 4 + 2];
                #pragma unroll
                for (int i = 0; i < 4; i++) {
                    acc[i][j] = ffma2(a[i].x, wlo, acc[i][j]);
                    acc[i][j] = ffma2(a[i].y, whi, acc[i][j]);
                }
            }
        }
        if (more) {
            const int nb = (ch + 1) & 1;
            *(float4*)&As[nb][mr0][kf] = va0;
            *(float4*)&As[nb][mr1][kf] = va1;
            *(float2*)&Wsm[nb][mr0][kf]     = make_float2(vw0.x, vw0.y);
            *(float2*)&Wsm[nb][mr0][kf + 2] = make_float2(vw0.z, vw0.w);
            *(float2*)&Wsm[nb][mr1][kf]     = make_float2(vw1.x, vw1.y);
            *(float2*)&Wsm[nb][mr1][kf + 2] = make_float2(vw1.z, vw1.w);
        }
        __syncthreads();
    }

    float vals[4][4];
    #pragma unroll
    for (int i = 0; i < 4; i++)
        #pragma unroll
        for (int j = 0; j < 4; j++) vals[i][j] = unpack_sum(acc[i][j]);

    if (g.nsplit == 1) {
        #pragma unroll
        for (int i = 0; i < 4; i++)
            #pragma unroll
            for (int j = 0; j < 4; j++) {
                int ng = n0 + c + 16 * j;
                if (ng < g.Nlim)
                    g.out[(size_t)(mt + i) * g.ldo + ng] =
                        epilogue_fn(g, vals[i][j], mt + i, ng);
            }
        return;
    }

    // ---- split-K: write partials; last-arriving CTA reduces with 256 threads ----
    float* p = &g_part[(size_t)(tile * g.nsplit + s) * 4096];
    #pragma unroll
    for (int i = 0; i < 4; i++)
        #pragma unroll
        for (int j = 0; j < 4; j++)
            __stcg(&p[(mt + i) * 64 + c + 16 * j], vals[i][j]);
    __threadfence();
    __syncthreads();
    if (tid == 0) {
        unsigned prev = atomicAdd(&g.ctr[tile], 1u);
        lastFlag = (prev == (unsigned)(g.nsplit - 1));
    }
    __syncthreads();
    if (!lastFlag) return;
    __threadfence();

    const float* pt = &g_part[(size_t)tile * g.nsplit * 4096];
    #pragma unroll 4
    for (int e = tid; e < 4096; e += 256) {
        float v = 0.f;
        for (int ss = 0; ss < g.nsplit; ss++)
            v += __ldcg(pt + (size_t)ss * 4096 + e);
        int m = e >> 6, ng = n0 + (e & 63);
        g.out[(size_t)m * g.ldo + ng] = epilogue_fn(g, v, m, ng);
    }
    if (tid == 0) g.ctr[tile] = 0;  // reset for next graph replay
}

__global__ void coef_kernel(const float* __restrict__ Wsum, const float* __restrict__ bsum,
                            const float* __restrict__ actions) {
    if (threadIdx.x == 0) {
        const int rows[3] = {1, 3, 5};
        float wgt[3];
        for (int i = 0; i < 3; i++) {
            float acc = bsum[rows[i]];
            for (int j = 0; j < 12; j++) acc += Wsum[rows[i] * 12 + j] * actions[j];
            wgt[i] = acc;
        }
        float mx = fmaxf(wgt[0], fmaxf(wgt[1], wgt[2]));
        float e0 = expf(wgt[0] - mx), e1 = expf(wgt[1] - mx), e2 = expf(wgt[2] - mx);
        float ssum = e0 + e1 + e2;
        g_c[0] = e0 / ssum; g_c[1] = e1 / ssum; g_c[2] = e2 / ssum;
    }
}

extern "C" void kernel_launch(void* const* d_in, const int* in_sizes, int n_in,
                              void* d_out, int out_size) {
    (void)in_sizes; (void)n_in; (void)out_size;
    const float* wv      = (const float*)d_in[0];
    const float* h       = (const float*)d_in[1];
    const int*   bi      = (const int*)  d_in[2];
    const float* W0      = (const float*)d_in[3];
    const float* b0      = (const float*)d_in[4];
    const float* Ws      = (const float*)d_in[5];
    const float* bs      = (const float*)d_in[6];
    const float* W_out   = (const float*)d_in[7];
    const float* b_out   = (const float*)d_in[8];
    const float* W_sum   = (const float*)d_in[9];
    const float* b_sum   = (const float*)d_in[10];
    const float* actions = (const float*)d_in[11];

    float *gh, *go1, *go23, *go45;
    unsigned* gctr;
    cudaGetSymbolAddress((void**)&gh,   g_h);
    cudaGetSymbolAddress((void**)&go1,  g_out1);
    cudaGetSymbolAddress((void**)&go23, g_out23);
    cudaGetSymbolAddress((void**)&go45, g_out45);
    cudaGetSymbolAddress((void**)&gctr, g_ctr);

    coef_kernel<<<1, 32>>>(W_sum, b_sum, actions);

    unsigned ofs = 0;
    for (int t = 0; t < NSTEP; t++) {
        const float* hin  = (t == 0) ? h : gh + (size_t)(t & 1) * Bq * Hd;
        float*       hout = gh + (size_t)((t + 1) & 1) * Bq * Hd;

        {   // phase 1: out1 = tanh(h @ Ws0^T + wv[idx] @ W0^T + bs0 + b0)  (virtual K=2048)
            GArgs a = {};
            a.A = hin; a.lda = Hd; a.W = Ws; a.W2 = W0; a.bias = bs; a.bias2 = b0;
            a.wv = wv; a.idx = bi + (t + 1);
            a.nsplit = 16; a.split1 = 8; a.Nlim = Hd; a.kper = 128;
            a.ctr = gctr + ofs; ofs += 16;
            a.out = go1; a.ldo = Hd; a.mode = 0;
            gemm_tile<<<dim3(16, 16), 256>>>(a);
        }
        {   // phase 2: [out2 | out3] = [relu | sigmoid](out1 @ [Ws1;Ws2]^T + [bs1;bs2])
            GArgs a = {};
            a.A = go1; a.lda = Hd; a.W = Ws + (size_t)Hd * Hd; a.bias = bs + Hd;
            a.nsplit = 8; a.split1 = 8; a.Nlim = 2 * Hd; a.kper = 128;
            a.ctr = gctr + ofs; ofs += 32;
            a.out = go23; a.ldo = 2 * Hd; a.mode = 1;
            gemm_tile<<<dim3(32, 8), 256>>>(a);
        }
        {   // phase 3: [out4 | out5] = [tanh | relu](out3 @ [Ws3;Ws4]^T + [bs3;bs4])
            GArgs a = {};
            a.A = go23 + Hd; a.lda = 2 * Hd; a.W = Ws + (size_t)3 * Hd * Hd; a.bias = bs + 3 * Hd;
            a.nsplit = 8; a.split1 = 8; a.Nlim = 2 * Hd; a.kper = 128;
            a.ctr = gctr + ofs; ofs += 32;
            a.out = go45; a.ldo = 2 * Hd; a.mode = 2;
            gemm_tile<<<dim3(32, 8), 256>>>(a);
        }
        {   // phase 4: h_new = c2*tanh(out5 @ Ws5^T + bs5) + c0*out2 + c1*out4
            GArgs a = {};
            a.A = go45 + Hd; a.lda = 2 * Hd; a.W = Ws + (size_t)5 * Hd * Hd; a.bias = bs + 5 * Hd;
            a.nsplit = 8; a.split1 = 8; a.Nlim = Hd; a.kper = 128;
            a.ctr = gctr + ofs; ofs += 16;
            a.out = hout; a.ldo = Hd; a.mode = 3;
            a.e1 = go23; a.e2 = go45;
            gemm_tile<<<dim3(16, 8), 256>>>(a);
        }
    }

    {   // final: logits = h_final @ W_out^T + b_out   [64, 50000]
        GArgs a = {};
        a.A = gh + (size_t)(NSTEP & 1) * Bq * Hd; a.lda = Hd;
        a.W = W_out; a.bias = b_out;
        a.nsplit = 1; a.split1 = 1; a.Nlim = Cc; a.kper = Hd;
        a.out = (float*)d_out; a.ldo = Cc; a.mode = 4;
        gemm_tile<<<dim3((Cc + TN - 1) / TN, 1), 256>>>(a);
    }
}

// round 7
// speedup vs baseline: 3.0452x; 1.6812x over previous
#include <cuda_runtime.h>
#include <math.h>

#define Bq 64
#define Hd 1024
#define Tt 128
#define NSTEP 127
#define Cc 50000
#define GRID 256
#define TM 64
#define TN 64
#define KCH 32
#define AST 36     // A smem row stride (floats), float4-aligned
#define WST 34     // W smem row stride (floats), float2-aligned

// Scratch (no cudaMalloc allowed)
__device__ float g_h[2][Bq * Hd];
__device__ float g_out1[Bq * Hd];
__device__ float g_out23[Bq * 2 * Hd];
__device__ float g_out45[Bq * 2 * Hd];
__device__ float g_part[256 * 4096];
__device__ float g_c[3];
__device__ unsigned g_bar_cnt;
__device__ volatile unsigned g_bar_gen;
__device__ unsigned g_exit_cnt;

struct PArgs {
    const float* wv; const float* h; const int* bi;
    const float* W0; const float* b0;
    const float* Ws; const float* bs;
    const float* W_out; const float* b_out;
    const float* W_sum; const float* b_sum; const float* actions;
    float* out;
};

__device__ __forceinline__ unsigned long long ffma2(unsigned long long a,
                                                    unsigned long long b,
                                                    unsigned long long c) {
    unsigned long long d;
    asm("fma.rn.f32x2 %0, %1, %2, %3;" : "=l"(d) : "l"(a), "l"(b), "l"(c));
    return d;
}

__device__ __forceinline__ float unpack_sum(unsigned long long p) {
    float lo, hi;
    asm("mov.b64 {%0, %1}, %2;" : "=f"(lo), "=f"(hi) : "l"(p));
    return lo + hi;
}

// Grid-wide barrier. Safe: GRID=256 <= 148 SMs * 2 resident CTAs (launch_bounds(256,2)).
__device__ __forceinline__ void grid_barrier(unsigned target) {
    __syncthreads();
    if (threadIdx.x == 0) {
        __threadfence();                                  // release prior stores
        unsigned prev = atomicAdd(&g_bar_cnt, 1u);
        if (prev == GRID - 1u) {
            g_bar_cnt = 0u;
            __threadfence();
            g_bar_gen = target;                           // release the barrier
        } else {
            while (g_bar_gen < target) __nanosleep(64);
        }
        __threadfence();                                  // acquire
    }
    __syncthreads();
}

// vals[4][4] = A[64, KPER] @ W[64, KPER]^T for one 64x64 tile slice.
template<int KPER, bool GATHER>
__device__ __forceinline__ void gemm64(
    const float* A, int lda,
    const float* wv, const int* idx,
    const float* Wp, int kbase, int n0, int Nlim,
    float (*As)[TM][AST], float (*Wsm)[TN][WST],
    int tid, float vals[4][4])
{
    const int mr0 = tid >> 3, mr1 = mr0 + 32;
    const int kf  = (tid & 7) * 4;
    const float *arow0, *arow1;
    if (GATHER) {
        arow0 = wv + (size_t)__ldg(idx + mr0 * Tt) * Hd;
        arow1 = wv + (size_t)__ldg(idx + mr1 * Tt) * Hd;
    } else {
        arow0 = A + (size_t)mr0 * lda;
        arow1 = A + (size_t)mr1 * lda;
    }
    arow0 += kbase + kf; arow1 += kbase + kf;
    const bool wok0 = (n0 + mr0) < Nlim;
    const bool wok1 = (n0 + mr1) < Nlim;
    const float* wrow0 = Wp + (size_t)(n0 + mr0) * Hd + kbase + kf;
    const float* wrow1 = Wp + (size_t)(n0 + mr1) * Hd + kbase + kf;

    const int r  = tid >> 4;
    const int c  = tid & 15;
    const int mt = r * 4;

    unsigned long long acc[4][4];
    #pragma unroll
    for (int i = 0; i < 4; i++)
        #pragma unroll
        for (int j = 0; j < 4; j++) acc[i][j] = 0ull;

    const int nch = KPER / KCH;
    const float4 z4 = make_float4(0.f, 0.f, 0.f, 0.f);

    // Prologue: chunk 0 (A via L2 — intermediates are rewritten each step, L1 would be stale)
    float4 va0 = GATHER ? __ldg((const float4*)arow0) : __ldcg((const float4*)arow0);
    float4 va1 = GATHER ? __ldg((const float4*)arow1) : __ldcg((const float4*)arow1);
    float4 vw0 = wok0 ? __ldg((const float4*)wrow0) : z4;
    float4 vw1 = wok1 ? __ldg((const float4*)wrow1) : z4;
    *(float4*)&As[0][mr0][kf] = va0;
    *(float4*)&As[0][mr1][kf] = va1;
    *(float2*)&Wsm[0][mr0][kf]     = make_float2(vw0.x, vw0.y);
    *(float2*)&Wsm[0][mr0][kf + 2] = make_float2(vw0.z, vw0.w);
    *(float2*)&Wsm[0][mr1][kf]     = make_float2(vw1.x, vw1.y);
    *(float2*)&Wsm[0][mr1][kf + 2] = make_float2(vw1.z, vw1.w);
    __syncthreads();

    for (int ch = 0; ch < nch; ch++) {
        const int b = ch & 1;
        const bool more = (ch + 1) < nch;
        if (more) {
            const int o = (ch + 1) * KCH;
            va0 = GATHER ? __ldg((const float4*)(arow0 + o)) : __ldcg((const float4*)(arow0 + o));
            va1 = GATHER ? __ldg((const float4*)(arow1 + o)) : __ldcg((const float4*)(arow1 + o));
            vw0 = wok0 ? __ldg((const float4*)(wrow0 + o)) : z4;
            vw1 = wok1 ? __ldg((const float4*)(wrow1 + o)) : z4;
        }
        #pragma unroll
        for (int k4 = 0; k4 < KCH / 4; k4++) {
            ulonglong2 a[4];
            #pragma unroll
            for (int i = 0; i < 4; i++)
                a[i] = *(const ulonglong2*)&As[b][mt + i][k4 * 4];
            #pragma unroll
            for (int j = 0; j < 4; j++) {
                const int n = c + 16 * j;
                unsigned long long wlo = *(const unsigned long long*)&Wsm[b][n][k4 * 4];
                unsigned long long whi = *(const unsigned long long*)&Wsm[b][n][k4 * 4 + 2];
                #pragma unroll
                for (int i = 0; i < 4; i++) {
                    acc[i][j] = ffma2(a[i].x, wlo, acc[i][j]);
                    acc[i][j] = ffma2(a[i].y, whi, acc[i][j]);
                }
            }
        }
        if (more) {
            const int nb = (ch + 1) & 1;
            *(float4*)&As[nb][mr0][kf] = va0;
            *(float4*)&As[nb][mr1][kf] = va1;
            *(float2*)&Wsm[nb][mr0][kf]     = make_float2(vw0.x, vw0.y);
            *(float2*)&Wsm[nb][mr0][kf + 2] = make_float2(vw0.z, vw0.w);
            *(float2*)&Wsm[nb][mr1][kf]     = make_float2(vw1.x, vw1.y);
            *(float2*)&Wsm[nb][mr1][kf + 2] = make_float2(vw1.z, vw1.w);
        }
        __syncthreads();
    }

    #pragma unroll
    for (int i = 0; i < 4; i++)
        #pragma unroll
        for (int j = 0; j < 4; j++) vals[i][j] = unpack_sum(acc[i][j]);
}

// Store one 64x64 partial tile to g_part slot.
__device__ __forceinline__ void store_partial(int slot, int tid, const float vals[4][4]) {
    float* p = &g_part[(size_t)slot * 4096];
    const int mt = (tid >> 4) * 4;
    const int c  = tid & 15;
    #pragma unroll
    for (int i = 0; i < 4; i++)
        #pragma unroll
        for (int j = 0; j < 4; j++)
            __stcg(&p[(mt + i) * 64 + c + 16 * j], vals[i][j]);
}

// All-CTA parallel reduce of partials + activation + store.
// mode: 0 tanh | 1 relu/sigmoid | 2 tanh/relu | 3 combine
template<int NSPLIT, int TILES>
__device__ __forceinline__ void reduce_phase(
    int bid, int tid, const float* bias, const float* bias2,
    int mode, float* out, int ldo, const float* e1, const float* e2)
{
    const int per = TILES * 4096 / GRID;   // 256 or 512
    const int base = bid * per;
    #pragma unroll 2
    for (int i = tid; i < per; i += 256) {
        const int e = base + i;
        const int tile = e >> 12;
        const int local = e & 4095;
        const float* pt = &g_part[(size_t)(tile * NSPLIT) * 4096 + local];
        float v = 0.f;
        #pragma unroll
        for (int ss = 0; ss < NSPLIT; ss++) v += __ldcg(pt + ss * 4096);
        const int m  = local >> 6;
        const int ng = tile * 64 + (local & 63);
        v += __ldg(&bias[ng]);
        if (bias2) v += __ldg(&bias2[ng]);
        float r;
        switch (mode) {
            case 0: r = tanhf(v); break;
            case 1: r = (ng < Hd) ? fmaxf(v, 0.f) : (1.f / (1.f + expf(-v))); break;
            case 2: r = (ng < Hd) ? tanhf(v) : fmaxf(v, 0.f); break;
            default:
                r = g_c[2] * tanhf(v)
                  + g_c[0] * __ldcg(&e1[(size_t)m * 2 * Hd + ng])
                  + g_c[1] * __ldcg(&e2[(size_t)m * 2 * Hd + ng]);
        }
        __stcg(&out[(size_t)m * ldo + ng], r);
    }
}

__global__ void __launch_bounds__(256, 2) rnn_persistent(PArgs p) {
    __shared__ __align__(16) float As[2][TM][AST];
    __shared__ __align__(16) float Wsm[2][TN][WST];

    const int bid = blockIdx.x;
    const int tid = threadIdx.x;

    // Leaf-combine softmax coefficients (visible to all via barrier 1's release)
    if (bid == 0 && tid == 0) {
        const int rows[3] = {1, 3, 5};
        float wgt[3];
        for (int i = 0; i < 3; i++) {
            float acc = p.b_sum[rows[i]];
            for (int j = 0; j < 12; j++) acc += p.W_sum[rows[i] * 12 + j] * p.actions[j];
            wgt[i] = acc;
        }
        float mx = fmaxf(wgt[0], fmaxf(wgt[1], wgt[2]));
        float e0 = expf(wgt[0] - mx), e1 = expf(wgt[1] - mx), e2 = expf(wgt[2] - mx);
        float s = e0 + e1 + e2;
        g_c[0] = e0 / s; g_c[1] = e1 / s; g_c[2] = e2 / s;
    }

    unsigned bar = 0;
    float vals[4][4];
    float* gh0 = g_h[0];
    float* gh1 = g_h[1];

    for (int t = 0; t < NSTEP; t++) {
        const float* hin  = (t == 0) ? p.h : ((t & 1) ? gh1 : gh0);
        float*       hout = ((t + 1) & 1) ? gh1 : gh0;

        // phase 1: out1 = tanh(h @ Ws0^T + wv[idx] @ W0^T + bs0 + b0)  (virtual K=2048)
        {
            const int tile = bid >> 4, s = bid & 15;
            if (s < 8)
                gemm64<128, false>(hin, Hd, nullptr, nullptr,
                                   p.Ws, s * 128, tile * 64, Hd, As, Wsm, tid, vals);
            else
                gemm64<128, true>(nullptr, 0, p.wv, p.bi + (t + 1),
                                  p.W0, (s - 8) * 128, tile * 64, Hd, As, Wsm, tid, vals);
            store_partial(tile * 16 + s, tid, vals);
        }
        grid_barrier(++bar);
        reduce_phase<16, 16>(bid, tid, p.bs, p.b0, 0, g_out1, Hd, nullptr, nullptr);
        grid_barrier(++bar);

        // phase 2: [out2|out3] = [relu|sigmoid](out1 @ [Ws1;Ws2]^T + [bs1;bs2])
        {
            const int tile = bid >> 3, s = bid & 7;
            gemm64<128, false>(g_out1, Hd, nullptr, nullptr,
                               p.Ws + (size_t)Hd * Hd, s * 128, tile * 64, 2 * Hd,
                               As, Wsm, tid, vals);
            store_partial(tile * 8 + s, tid, vals);
        }
        grid_barrier(++bar);
        reduce_phase<8, 32>(bid, tid, p.bs + Hd, nullptr, 1, g_out23, 2 * Hd, nullptr, nullptr);
        grid_barrier(++bar);

        // phase 3: [out4|out5] = [tanh|relu](out3 @ [Ws3;Ws4]^T + [bs3;bs4])
        {
            const int tile = bid >> 3, s = bid & 7;
            gemm64<128, false>(g_out23 + Hd, 2 * Hd, nullptr, nullptr,
                               p.Ws + (size_t)3 * Hd * Hd, s * 128, tile * 64, 2 * Hd,
                               As, Wsm, tid, vals);
            store_partial(tile * 8 + s, tid, vals);
        }
        grid_barrier(++bar);
        reduce_phase<8, 32>(bid, tid, p.bs + 3 * Hd, nullptr, 2, g_out45, 2 * Hd, nullptr, nullptr);
        grid_barrier(++bar);

        // phase 4: h_new = c2*tanh(out5 @ Ws5^T + bs5) + c0*out2 + c1*out4
        {
            const int tile = bid >> 4, s = bid & 15;
            gemm64<64, false>(g_out45 + Hd, 2 * Hd, nullptr, nullptr,
                              p.Ws + (size_t)5 * Hd * Hd, s * 64, tile * 64, Hd,
                              As, Wsm, tid, vals);
            store_partial(tile * 16 + s, tid, vals);
        }
        grid_barrier(++bar);
        reduce_phase<16, 16>(bid, tid, p.bs + 5 * Hd, nullptr, 3, hout, Hd, g_out23, g_out45);
        grid_barrier(++bar);
    }

    // final: logits = h_final @ W_out^T + b_out  [64, 50000]; CTAs loop over N tiles
    {
        const float* hf = gh1;   // (126+1)&1 == 1
        const int ntiles = (Cc + TN - 1) / TN;   // 782
        const int mt = (tid >> 4) * 4;
        const int c  = tid & 15;
        for (int tile = bid; tile < ntiles; tile += GRID) {
            gemm64<Hd, false>(hf, Hd, nullptr, nullptr,
                              p.W_out, 0, tile * 64, Cc, As, Wsm, tid, vals);
            #pragma unroll
            for (int i = 0; i < 4; i++)
                #pragma unroll
                for (int j = 0; j < 4; j++) {
                    const int ng = tile * 64 + c + 16 * j;
                    if (ng < Cc)
                        p.out[(size_t)(mt + i) * Cc + ng] = vals[i][j] + __ldg(&p.b_out[ng]);
                }
        }
    }

    // exit handshake: last CTA out resets barrier state for the next graph replay
    __threadfence();
    __syncthreads();
    if (tid == 0) {
        unsigned prev = atomicAdd(&g_exit_cnt, 1u);
        if (prev == GRID - 1u) {
            g_exit_cnt = 0u;
            g_bar_cnt  = 0u;
            g_bar_gen  = 0u;
            __threadfence();
        }
    }
}

extern "C" void kernel_launch(void* const* d_in, const int* in_sizes, int n_in,
                              void* d_out, int out_size) {
    (void)in_sizes; (void)n_in; (void)out_size;
    PArgs p;
    p.wv      = (const float*)d_in[0];
    p.h       = (const float*)d_in[1];
    p.bi      = (const int*)  d_in[2];
    p.W0      = (const float*)d_in[3];
    p.b0      = (const float*)d_in[4];
    p.Ws      = (const float*)d_in[5];
    p.bs      = (const float*)d_in[6];
    p.W_out   = (const float*)d_in[7];
    p.b_out   = (const float*)d_in[8];
    p.W_sum   = (const float*)d_in[9];
    p.b_sum   = (const float*)d_in[10];
    p.actions = (const float*)d_in[11];
    p.out     = (float*)d_out;

    rnn_persistent<<<GRID, 256>>>(p);
}

// round 8
// speedup vs baseline: 3.0537x; 1.0028x over previous
#include <cuda_runtime.h>
#include <math.h>

#define Bq 64
#define Hd 1024
#define Tt 128
#define NSTEP 127
#define Cc 50000
#define GRID 256
#define TM 64
#define TN 64
#define KCH 32
#define AST 36     // A smem row stride (floats), float4-aligned
#define WST 34     // W smem row stride (floats), float2-aligned

// Scratch (no cudaMalloc allowed)
__device__ float g_h[2][Bq * Hd];
__device__ float g_out1[Bq * Hd];
__device__ float g_out23[Bq * 2 * Hd];
__device__ float g_out45[Bq * 2 * Hd];
__device__ float g_part[256 * 4096];
__device__ float g_c[3];
__device__ unsigned g_bar_cnt;
__device__ volatile unsigned g_bar_gen;
__device__ unsigned g_exit_cnt;

struct PArgs {
    const float* wv; const float* h; const int* bi;
    const float* W0; const float* b0;
    const float* Ws; const float* bs;
    const float* W_out; const float* b_out;
    const float* W_sum; const float* b_sum; const float* actions;
    float* out;
};

__device__ __forceinline__ unsigned long long ffma2(unsigned long long a,
                                                    unsigned long long b,
                                                    unsigned long long c) {
    unsigned long long d;
    asm("fma.rn.f32x2 %0, %1, %2, %3;" : "=l"(d) : "l"(a), "l"(b), "l"(c));
    return d;
}

__device__ __forceinline__ float unpack_sum(unsigned long long p) {
    float lo, hi;
    asm("mov.b64 {%0, %1}, %2;" : "=f"(lo), "=f"(hi) : "l"(p));
    return lo + hi;
}

// Grid-wide barrier. Safe: GRID=256 <= 148 SMs * 2 resident CTAs (launch_bounds(256,2)).
__device__ __forceinline__ void grid_barrier(unsigned target) {
    __syncthreads();
    if (threadIdx.x == 0) {
        __threadfence();                                  // release prior stores
        unsigned prev = atomicAdd(&g_bar_cnt, 1u);
        if (prev == GRID - 1u) {
            g_bar_cnt = 0u;
            __threadfence();
            g_bar_gen = target;                           // release the barrier
        } else {
            while (g_bar_gen < target) __nanosleep(64);
        }
        __threadfence();                                  // acquire
    }
    __syncthreads();
}

// vals[4][4] = A[64, KPER] @ W[64, KPER]^T for one 64x64 tile slice.
template<int KPER, bool GATHER>
__device__ __forceinline__ void gemm64(
    const float* A, int lda,
    const float* wv, const int* idx,
    const float* Wp, int kbase, int n0, int Nlim,
    float (*As)[TM][AST], float (*Wsm)[TN][WST],
    int tid, float vals[4][4])
{
    const int mr0 = tid >> 3, mr1 = mr0 + 32;
    const int kf  = (tid & 7) * 4;
    const float *arow0, *arow1;
    if (GATHER) {
        arow0 = wv + (size_t)__ldg(idx + mr0 * Tt) * Hd;
        arow1 = wv + (size_t)__ldg(idx + mr1 * Tt) * Hd;
    } else {
        arow0 = A + (size_t)mr0 * lda;
        arow1 = A + (size_t)mr1 * lda;
    }
    arow0 += kbase + kf; arow1 += kbase + kf;
    const bool wok0 = (n0 + mr0) < Nlim;
    const bool wok1 = (n0 + mr1) < Nlim;
    const float* wrow0 = Wp + (size_t)(n0 + mr0) * Hd + kbase + kf;
    const float* wrow1 = Wp + (size_t)(n0 + mr1) * Hd + kbase + kf;

    const int r  = tid >> 4;
    const int c  = tid & 15;
    const int mt = r * 4;

    unsigned long long acc[4][4];
    #pragma unroll
    for (int i = 0; i < 4; i++)
        #pragma unroll
        for (int j = 0; j < 4; j++) acc[i][j] = 0ull;

    const int nch = KPER / KCH;
    const float4 z4 = make_float4(0.f, 0.f, 0.f, 0.f);

    // Prologue: chunk 0 (A via L2 — intermediates are rewritten each step, L1 would be stale)
    float4 va0 = GATHER ? __ldg((const float4*)arow0) : __ldcg((const float4*)arow0);
    float4 va1 = GATHER ? __ldg((const float4*)arow1) : __ldcg((const float4*)arow1);
    float4 vw0 = wok0 ? __ldg((const float4*)wrow0) : z4;
    float4 vw1 = wok1 ? __ldg((const float4*)wrow1) : z4;
    *(float4*)&As[0][mr0][kf] = va0;
    *(float4*)&As[0][mr1][kf] = va1;
    *(float2*)&Wsm[0][mr0][kf]     = make_float2(vw0.x, vw0.y);
    *(float2*)&Wsm[0][mr0][kf + 2] = make_float2(vw0.z, vw0.w);
    *(float2*)&Wsm[0][mr1][kf]     = make_float2(vw1.x, vw1.y);
    *(float2*)&Wsm[0][mr1][kf + 2] = make_float2(vw1.z, vw1.w);
    __syncthreads();

    for (int ch = 0; ch < nch; ch++) {
        const int b = ch & 1;
        const bool more = (ch + 1) < nch;
        if (more) {
            const int o = (ch + 1) * KCH;
            va0 = GATHER ? __ldg((const float4*)(arow0 + o)) : __ldcg((const float4*)(arow0 + o));
            va1 = GATHER ? __ldg((const float4*)(arow1 + o)) : __ldcg((const float4*)(arow1 + o));
            vw0 = wok0 ? __ldg((const float4*)(wrow0 + o)) : z4;
            vw1 = wok1 ? __ldg((const float4*)(wrow1 + o)) : z4;
        }
        #pragma unroll
        for (int k4 = 0; k4 < KCH / 4; k4++) {
            ulonglong2 a[4];
            #pragma unroll
            for (int i = 0; i < 4; i++)
                a[i] = *(const ulonglong2*)&As[b][mt + i][k4 * 4];
            #pragma unroll
            for (int j = 0; j < 4; j++) {
                const int n = c + 16 * j;
                unsigned long long wlo = *(const unsigned long long*)&Wsm[b][n][k4 * 4];
                unsigned long long whi = *(const unsigned long long*)&Wsm[b][n][k4 * 4 + 2];
                #pragma unroll
                for (int i = 0; i < 4; i++) {
                    acc[i][j] = ffma2(a[i].x, wlo, acc[i][j]);
                    acc[i][j] = ffma2(a[i].y, whi, acc[i][j]);
                }
            }
        }
        if (more) {
            const int nb = (ch + 1) & 1;
            *(float4*)&As[nb][mr0][kf] = va0;
            *(float4*)&As[nb][mr1][kf] = va1;
            *(float2*)&Wsm[nb][mr0][kf]     = make_float2(vw0.x, vw0.y);
            *(float2*)&Wsm[nb][mr0][kf + 2] = make_float2(vw0.z, vw0.w);
            *(float2*)&Wsm[nb][mr1][kf]     = make_float2(vw1.x, vw1.y);
            *(float2*)&Wsm[nb][mr1][kf + 2] = make_float2(vw1.z, vw1.w);
        }
        __syncthreads();
    }

    #pragma unroll
    for (int i = 0; i < 4; i++)
        #pragma unroll
        for (int j = 0; j < 4; j++) vals[i][j] = unpack_sum(acc[i][j]);
}

// Store one 64x64 partial tile to g_part slot.
__device__ __forceinline__ void store_partial(int slot, int tid, const float vals[4][4]) {
    float* p = &g_part[(size_t)slot * 4096];
    const int mt = (tid >> 4) * 4;
    const int c  = tid & 15;
    #pragma unroll
    for (int i = 0; i < 4; i++)
        #pragma unroll
        for (int j = 0; j < 4; j++)
            __stcg(&p[(mt + i) * 64 + c + 16 * j], vals[i][j]);
}

// All-CTA parallel reduce of partials + activation + store.
// mode: 0 tanh | 1 relu/sigmoid | 2 tanh/relu | 3 combine
template<int NSPLIT, int TILES>
__device__ __forceinline__ void reduce_phase(
    int bid, int tid, const float* bias, const float* bias2,
    int mode, float* out, int ldo, const float* e1, const float* e2)
{
    const int per = TILES * 4096 / GRID;   // 256 or 512
    const int base = bid * per;
    #pragma unroll 2
    for (int i = tid; i < per; i += 256) {
        const int e = base + i;
        const int tile = e >> 12;
        const int local = e & 4095;
        const float* pt = &g_part[(size_t)(tile * NSPLIT) * 4096 + local];
        float v = 0.f;
        #pragma unroll
        for (int ss = 0; ss < NSPLIT; ss++) v += __ldcg(pt + ss * 4096);
        const int m  = local >> 6;
        const int ng = tile * 64 + (local & 63);
        v += __ldg(&bias[ng]);
        if (bias2) v += __ldg(&bias2[ng]);
        float r;
        switch (mode) {
            case 0: r = tanhf(v); break;
            case 1: r = (ng < Hd) ? fmaxf(v, 0.f) : (1.f / (1.f + expf(-v))); break;
            case 2: r = (ng < Hd) ? tanhf(v) : fmaxf(v, 0.f); break;
            default:
                r = g_c[2] * tanhf(v)
                  + g_c[0] * __ldcg(&e1[(size_t)m * 2 * Hd + ng])
                  + g_c[1] * __ldcg(&e2[(size_t)m * 2 * Hd + ng]);
        }
        __stcg(&out[(size_t)m * ldo + ng], r);
    }
}

__global__ void __launch_bounds__(256, 2) rnn_persistent(PArgs p) {
    __shared__ __align__(16) float As[2][TM][AST];
    __shared__ __align__(16) float Wsm[2][TN][WST];

    const int bid = blockIdx.x;
    const int tid = threadIdx.x;

    // Leaf-combine softmax coefficients (visible to all via barrier 1's release)
    if (bid == 0 && tid == 0) {
        const int rows[3] = {1, 3, 5};
        float wgt[3];
        for (int i = 0; i < 3; i++) {
            float acc = p.b_sum[rows[i]];
            for (int j = 0; j < 12; j++) acc += p.W_sum[rows[i] * 12 + j] * p.actions[j];
            wgt[i] = acc;
        }
        float mx = fmaxf(wgt[0], fmaxf(wgt[1], wgt[2]));
        float e0 = expf(wgt[0] - mx), e1 = expf(wgt[1] - mx), e2 = expf(wgt[2] - mx);
        float s = e0 + e1 + e2;
        g_c[0] = e0 / s; g_c[1] = e1 / s; g_c[2] = e2 / s;
    }

    unsigned bar = 0;
    float vals[4][4];
    float* gh0 = g_h[0];
    float* gh1 = g_h[1];

    for (int t = 0; t < NSTEP; t++) {
        const float* hin  = (t == 0) ? p.h : ((t & 1) ? gh1 : gh0);
        float*       hout = ((t + 1) & 1) ? gh1 : gh0;

        // phase 1: out1 = tanh(h @ Ws0^T + wv[idx] @ W0^T + bs0 + b0)  (virtual K=2048)
        {
            const int tile = bid >> 4, s = bid & 15;
            if (s < 8)
                gemm64<128, false>(hin, Hd, nullptr, nullptr,
                                   p.Ws, s * 128, tile * 64, Hd, As, Wsm, tid, vals);
            else
                gemm64<128, true>(nullptr, 0, p.wv, p.bi + (t + 1),
                                  p.W0, (s - 8) * 128, tile * 64, Hd, As, Wsm, tid, vals);
            store_partial(tile * 16 + s, tid, vals);
        }
        grid_barrier(++bar);
        reduce_phase<16, 16>(bid, tid, p.bs, p.b0, 0, g_out1, Hd, nullptr, nullptr);
        grid_barrier(++bar);

        // phase 2: [out2|out3] = [relu|sigmoid](out1 @ [Ws1;Ws2]^T + [bs1;bs2])
        {
            const int tile = bid >> 3, s = bid & 7;
            gemm64<128, false>(g_out1, Hd, nullptr, nullptr,
                               p.Ws + (size_t)Hd * Hd, s * 128, tile * 64, 2 * Hd,
                               As, Wsm, tid, vals);
            store_partial(tile * 8 + s, tid, vals);
        }
        grid_barrier(++bar);
        reduce_phase<8, 32>(bid, tid, p.bs + Hd, nullptr, 1, g_out23, 2 * Hd, nullptr, nullptr);
        grid_barrier(++bar);

        // phase 3: [out4|out5] = [tanh|relu](out3 @ [Ws3;Ws4]^T + [bs3;bs4])
        {
            const int tile = bid >> 3, s = bid & 7;
            gemm64<128, false>(g_out23 + Hd, 2 * Hd, nullptr, nullptr,
                               p.Ws + (size_t)3 * Hd * Hd, s * 128, tile * 64, 2 * Hd,
                               As, Wsm, tid, vals);
            store_partial(tile * 8 + s, tid, vals);
        }
        grid_barrier(++bar);
        reduce_phase<8, 32>(bid, tid, p.bs + 3 * Hd, nullptr, 2, g_out45, 2 * Hd, nullptr, nullptr);
        grid_barrier(++bar);

        // phase 4: h_new = c2*tanh(out5 @ Ws5^T + bs5) + c0*out2 + c1*out4
        {
            const int tile = bid >> 4, s = bid & 15;
            gemm64<64, false>(g_out45 + Hd, 2 * Hd, nullptr, nullptr,
                              p.Ws + (size_t)5 * Hd * Hd, s * 64, tile * 64, Hd,
                              As, Wsm, tid, vals);
            store_partial(tile * 16 + s, tid, vals);
        }
        grid_barrier(++bar);
        reduce_phase<16, 16>(bid, tid, p.bs + 5 * Hd, nullptr, 3, hout, Hd, g_out23, g_out45);
        grid_barrier(++bar);
    }

    // final: logits = h_final @ W_out^T + b_out  [64, 50000]; CTAs loop over N tiles
    {
        const float* hf = gh1;   // (126+1)&1 == 1
        const int ntiles = (Cc + TN - 1) / TN;   // 782
        const int mt = (tid >> 4) * 4;
        const int c  = tid & 15;
        for (int tile = bid; tile < ntiles; tile += GRID) {
            gemm64<Hd, false>(hf, Hd, nullptr, nullptr,
                              p.W_out, 0, tile * 64, Cc, As, Wsm, tid, vals);
            #pragma unroll
            for (int i = 0; i < 4; i++)
                #pragma unroll
                for (int j = 0; j < 4; j++) {
                    const int ng = tile * 64 + c + 16 * j;
                    if (ng < Cc)
                        p.out[(size_t)(mt + i) * Cc + ng] = vals[i][j] + __ldg(&p.b_out[ng]);
                }
        }
    }

    // exit handshake: last CTA out resets barrier state for the next graph replay
    __threadfence();
    __syncthreads();
    if (tid == 0) {
        unsigned prev = atomicAdd(&g_exit_cnt, 1u);
        if (prev == GRID - 1u) {
            g_exit_cnt = 0u;
            g_bar_cnt  = 0u;
            g_bar_gen  = 0u;
            __threadfence();
        }
    }
}

extern "C" void kernel_launch(void* const* d_in, const int* in_sizes, int n_in,
                              void* d_out, int out_size) {
    (void)in_sizes; (void)n_in; (void)out_size;
    PArgs p;
    p.wv      = (const float*)d_in[0];
    p.h       = (const float*)d_in[1];
    p.bi      = (const int*)  d_in[2];
    p.W0      = (const float*)d_in[3];
    p.b0      = (const float*)d_in[4];
    p.Ws      = (const float*)d_in[5];
    p.bs      = (const float*)d_in[6];
    p.W_out   = (const float*)d_in[7];
    p.b_out   = (const float*)d_in[8];
    p.W_sum   = (const float*)d_in[9];
    p.b_sum   = (const float*)d_in[10];
    p.actions = (const float*)d_in[11];
    p.out     = (float*)d_out;

    rnn_persistent<<<GRID, 256>>>(p);
}

// round 9
// speedup vs baseline: 3.1776x; 1.0406x over previous
#include <cuda_runtime.h>
#include <math.h>

#define Bq 64
#define Hd 1024
#define Tt 128
#define NSTEP 127
#define Cc 50000
#define GRID 256
#define TM 64
#define TN 64
#define KCH 32
#define AST 36     // A smem row stride (floats), float4-aligned
#define WST 34     // W smem row stride (floats), float2-aligned

// Scratch (no cudaMalloc allowed)
__device__ float g_h[2][Bq * Hd];
__device__ float g_out1[Bq * Hd];
__device__ float g_out23[Bq * 2 * Hd];
__device__ float g_out45[Bq * 2 * Hd];
__device__ float g_part[256 * 4096];
__device__ float g_c[3];
__device__ unsigned g_tile_ctr[96];       // epoch counters: ph1:0-15, ph2:16-47, ph3:48-79, ph4:80-95
__device__ unsigned g_bar_cnt;
__device__ volatile unsigned g_bar_gen;
__device__ unsigned g_exit_cnt;

struct PArgs {
    const float* wv; const float* h; const int* bi;
    const float* W0; const float* b0;
    const float* Ws; const float* bs;
    const float* W_out; const float* b_out;
    const float* W_sum; const float* b_sum; const float* actions;
    float* out;
};

__device__ __forceinline__ unsigned long long ffma2(unsigned long long a,
                                                    unsigned long long b,
                                                    unsigned long long c) {
    unsigned long long d;
    asm("fma.rn.f32x2 %0, %1, %2, %3;" : "=l"(d) : "l"(a), "l"(b), "l"(c));
    return d;
}

__device__ __forceinline__ float unpack_sum(unsigned long long p) {
    float lo, hi;
    asm("mov.b64 {%0, %1}, %2;" : "=f"(lo), "=f"(hi) : "l"(p));
    return lo + hi;
}

// Grid-wide barrier. Safe: GRID=256 <= 148 SMs * 2 resident CTAs (launch_bounds(256,2)).
__device__ __forceinline__ void grid_barrier(unsigned target) {
    __syncthreads();
    if (threadIdx.x == 0) {
        __threadfence();
        unsigned prev = atomicAdd(&g_bar_cnt, 1u);
        if (prev == GRID - 1u) {
            g_bar_cnt = 0u;
            __threadfence();
            g_bar_gen = target;
        } else {
            while (g_bar_gen < target) __nanosleep(32);
        }
        __threadfence();
    }
    __syncthreads();
}

// Per-tile group sync: nsplit CTAs of one tile arrive on a monotone epoch counter.
__device__ __forceinline__ void group_sync(unsigned* ctr, unsigned target) {
    __syncthreads();
    if (threadIdx.x == 0) {
        __threadfence();
        atomicAdd(ctr, 1u);
        while (*(volatile unsigned*)ctr < target) __nanosleep(32);
        __threadfence();
    }
    __syncthreads();
}

// vals[4][4] = A[64, KPER] @ W[64, KPER]^T for one 64x64 tile slice.
template<int KPER, bool GATHER>
__device__ __forceinline__ void gemm64(
    const float* A, int lda,
    const float* wv, const int* idx,
    const float* Wp, int kbase, int n0, int Nlim,
    float (*As)[TM][AST], float (*Wsm)[TN][WST],
    int tid, float vals[4][4])
{
    const int mr0 = tid >> 3, mr1 = mr0 + 32;
    const int kf  = (tid & 7) * 4;
    const float *arow0, *arow1;
    if (GATHER) {
        arow0 = wv + (size_t)__ldg(idx + mr0 * Tt) * Hd;
        arow1 = wv + (size_t)__ldg(idx + mr1 * Tt) * Hd;
    } else {
        arow0 = A + (size_t)mr0 * lda;
        arow1 = A + (size_t)mr1 * lda;
    }
    arow0 += kbase + kf; arow1 += kbase + kf;
    const bool wok0 = (n0 + mr0) < Nlim;
    const bool wok1 = (n0 + mr1) < Nlim;
    const float* wrow0 = Wp + (size_t)(n0 + mr0) * Hd + kbase + kf;
    const float* wrow1 = Wp + (size_t)(n0 + mr1) * Hd + kbase + kf;

    const int r  = tid >> 4;
    const int c  = tid & 15;
    const int mt = r * 4;

    unsigned long long acc[4][4];
    #pragma unroll
    for (int i = 0; i < 4; i++)
        #pragma unroll
        for (int j = 0; j < 4; j++) acc[i][j] = 0ull;

    const int nch = KPER / KCH;
    const float4 z4 = make_float4(0.f, 0.f, 0.f, 0.f);

    float4 va0 = GATHER ? __ldg((const float4*)arow0) : __ldcg((const float4*)arow0);
    float4 va1 = GATHER ? __ldg((const float4*)arow1) : __ldcg((const float4*)arow1);
    float4 vw0 = wok0 ? __ldg((const float4*)wrow0) : z4;
    float4 vw1 = wok1 ? __ldg((const float4*)wrow1) : z4;
    *(float4*)&As[0][mr0][kf] = va0;
    *(float4*)&As[0][mr1][kf] = va1;
    *(float2*)&Wsm[0][mr0][kf]     = make_float2(vw0.x, vw0.y);
    *(float2*)&Wsm[0][mr0][kf + 2] = make_float2(vw0.z, vw0.w);
    *(float2*)&Wsm[0][mr1][kf]     = make_float2(vw1.x, vw1.y);
    *(float2*)&Wsm[0][mr1][kf + 2] = make_float2(vw1.z, vw1.w);
    __syncthreads();

    for (int ch = 0; ch < nch; ch++) {
        const int b = ch & 1;
        const bool more = (ch + 1) < nch;
        if (more) {
            const int o = (ch + 1) * KCH;
            va0 = GATHER ? __ldg((const float4*)(arow0 + o)) : __ldcg((const float4*)(arow0 + o));
            va1 = GATHER ? __ldg((const float4*)(arow1 + o)) : __ldcg((const float4*)(arow1 + o));
            vw0 = wok0 ? __ldg((const float4*)(wrow0 + o)) : z4;
            vw1 = wok1 ? __ldg((const float4*)(wrow1 + o)) : z4;
        }
        #pragma unroll
        for (int k4 = 0; k4 < KCH / 4; k4++) {
            ulonglong2 a[4];
            #pragma unroll
            for (int i = 0; i < 4; i++)
                a[i] = *(const ulonglong2*)&As[b][mt + i][k4 * 4];
            #pragma unroll
            for (int j = 0; j < 4; j++) {
                const int n = c + 16 * j;
                unsigned long long wlo = *(const unsigned long long*)&Wsm[b][n][k4 * 4];
                unsigned long long whi = *(const unsigned long long*)&Wsm[b][n][k4 * 4 + 2];
                #pragma unroll
                for (int i = 0; i < 4; i++) {
                    acc[i][j] = ffma2(a[i].x, wlo, acc[i][j]);
                    acc[i][j] = ffma2(a[i].y, whi, acc[i][j]);
                }
            }
        }
        if (more) {
            const int nb = (ch + 1) & 1;
            *(float4*)&As[nb][mr0][kf] = va0;
            *(float4*)&As[nb][mr1][kf] = va1;
            *(float2*)&Wsm[nb][mr0][kf]     = make_float2(vw0.x, vw0.y);
            *(float2*)&Wsm[nb][mr0][kf + 2] = make_float2(vw0.z, vw0.w);
            *(float2*)&Wsm[nb][mr1][kf]     = make_float2(vw1.x, vw1.y);
            *(float2*)&Wsm[nb][mr1][kf + 2] = make_float2(vw1.z, vw1.w);
        }
        __syncthreads();
    }

    #pragma unroll
    for (int i = 0; i < 4; i++)
        #pragma unroll
        for (int j = 0; j < 4; j++) vals[i][j] = unpack_sum(acc[i][j]);
}

__device__ __forceinline__ void store_partial(int slot, int tid, const float vals[4][4]) {
    float* p = &g_part[(size_t)slot * 4096];
    const int mt = (tid >> 4) * 4;
    const int c  = tid & 15;
    #pragma unroll
    for (int i = 0; i < 4; i++)
        #pragma unroll
        for (int j = 0; j < 4; j++)
            __stcg(&p[(mt + i) * 64 + c + 16 * j], vals[i][j]);
}

// Group reduce: CTA s of a tile reduces its 4096/NSPLIT slice + bias + activation.
// mode: 0 tanh | 1 relu/sigmoid | 2 tanh/relu | 3 combine
template<int NSPLIT>
__device__ __forceinline__ void group_reduce(
    int tile, int s, int tid, const float* bias, const float* bias2,
    int mode, float* out, int ldo, const float* e1, const float* e2)
{
    const int per = 4096 / NSPLIT;     // 256 (nsplit 16) or 512 (nsplit 8)
    const float* pt = &g_part[(size_t)(tile * NSPLIT) * 4096];
    #pragma unroll 2
    for (int i = tid; i < per; i += 256) {
        const int local = s * per + i;
        float v = 0.f;
        #pragma unroll
        for (int ss = 0; ss < NSPLIT; ss++) v += __ldcg(pt + ss * 4096 + local);
        const int m  = local >> 6;
        const int ng = tile * 64 + (local & 63);
        v += __ldg(&bias[ng]);
        if (bias2) v += __ldg(&bias2[ng]);
        float r;
        switch (mode) {
            case 0: r = tanhf(v); break;
            case 1: r = (ng < Hd) ? fmaxf(v, 0.f) : (1.f / (1.f + expf(-v))); break;
            case 2: r = (ng < Hd) ? tanhf(v) : fmaxf(v, 0.f); break;
            default:
                r = g_c[2] * tanhf(v)
                  + g_c[0] * __ldcg(&e1[(size_t)m * 2 * Hd + ng])
                  + g_c[1] * __ldcg(&e2[(size_t)m * 2 * Hd + ng]);
        }
        __stcg(&out[(size_t)m * ldo + ng], r);
    }
}

__global__ void __launch_bounds__(256, 2) rnn_persistent(PArgs p) {
    __shared__ __align__(16) float As[2][TM][AST];
    __shared__ __align__(16) float Wsm[2][TN][WST];

    const int bid = blockIdx.x;
    const int tid = threadIdx.x;

    if (bid == 0 && tid == 0) {
        const int rows[3] = {1, 3, 5};
        float wgt[3];
        for (int i = 0; i < 3; i++) {
            float acc = p.b_sum[rows[i]];
            for (int j = 0; j < 12; j++) acc += p.W_sum[rows[i] * 12 + j] * p.actions[j];
            wgt[i] = acc;
        }
        float mx = fmaxf(wgt[0], fmaxf(wgt[1], wgt[2]));
        float e0 = expf(wgt[0] - mx), e1 = expf(wgt[1] - mx), e2 = expf(wgt[2] - mx);
        float s = e0 + e1 + e2;
        g_c[0] = e0 / s; g_c[1] = e1 / s; g_c[2] = e2 / s;
    }

    unsigned bar = 0;
    float vals[4][4];
    float* gh0 = g_h[0];
    float* gh1 = g_h[1];

    const int tile16 = bid >> 4, s16 = bid & 15;
    const int tile8  = bid >> 3, s8  = bid & 7;

    for (int t = 0; t < NSTEP; t++) {
        const float* hin  = (t == 0) ? p.h : ((t & 1) ? gh1 : gh0);
        float*       hout = ((t + 1) & 1) ? gh1 : gh0;

        // phase 1: out1 = tanh(h @ Ws0^T + wv[idx] @ W0^T + bs0 + b0)  (virtual K=2048, nsplit=16)
        if (s16 < 8)
            gemm64<128, false>(hin, Hd, nullptr, nullptr,
                               p.Ws, s16 * 128, tile16 * 64, Hd, As, Wsm, tid, vals);
        else
            gemm64<128, true>(nullptr, 0, p.wv, p.bi + (t + 1),
                              p.W0, (s16 - 8) * 128, tile16 * 64, Hd, As, Wsm, tid, vals);
        store_partial(tile16 * 16 + s16, tid, vals);
        group_sync(&g_tile_ctr[tile16], (unsigned)(t + 1) * 16u);
        group_reduce<16>(tile16, s16, tid, p.bs, p.b0, 0, g_out1, Hd, nullptr, nullptr);
        grid_barrier(++bar);

        // phase 2: [out2|out3] = [relu|sigmoid](out1 @ [Ws1;Ws2]^T + [bs1;bs2])  (nsplit=8)
        gemm64<128, false>(g_out1, Hd, nullptr, nullptr,
                           p.Ws + (size_t)Hd * Hd, s8 * 128, tile8 * 64, 2 * Hd,
                           As, Wsm, tid, vals);
        store_partial(tile8 * 8 + s8, tid, vals);
        group_sync(&g_tile_ctr[16 + tile8], (unsigned)(t + 1) * 8u);
        group_reduce<8>(tile8, s8, tid, p.bs + Hd, nullptr, 1, g_out23, 2 * Hd, nullptr, nullptr);
        grid_barrier(++bar);

        // phase 3: [out4|out5] = [tanh|relu](out3 @ [Ws3;Ws4]^T + [bs3;bs4])  (nsplit=8)
        gemm64<128, false>(g_out23 + Hd, 2 * Hd, nullptr, nullptr,
                           p.Ws + (size_t)3 * Hd * Hd, s8 * 128, tile8 * 64, 2 * Hd,
                           As, Wsm, tid, vals);
        store_partial(tile8 * 8 + s8, tid, vals);
        group_sync(&g_tile_ctr[48 + tile8], (unsigned)(t + 1) * 8u);
        group_reduce<8>(tile8, s8, tid, p.bs + 3 * Hd, nullptr, 2, g_out45, 2 * Hd, nullptr, nullptr);
        grid_barrier(++bar);

        // phase 4: h_new = c2*tanh(out5 @ Ws5^T + bs5) + c0*out2 + c1*out4  (nsplit=16, kper=64)
        gemm64<64, false>(g_out45 + Hd, 2 * Hd, nullptr, nullptr,
                          p.Ws + (size_t)5 * Hd * Hd, s16 * 64, tile16 * 64, Hd,
                          As, Wsm, tid, vals);
        store_partial(tile16 * 16 + s16, tid, vals);
        group_sync(&g_tile_ctr[80 + tile16], (unsigned)(t + 1) * 16u);
        group_reduce<16>(tile16, s16, tid, p.bs + 5 * Hd, nullptr, 3, hout, Hd, g_out23, g_out45);
        grid_barrier(++bar);
    }

    // final: logits = h_final @ W_out^T + b_out  [64, 50000]
    {
        const float* hf = gh1;   // (126+1)&1 == 1
        const int ntiles = (Cc + TN - 1) / TN;   // 782
        const int mt = (tid >> 4) * 4;
        const int c  = tid & 15;
        for (int tile = bid; tile < ntiles; tile += GRID) {
            gemm64<Hd, false>(hf, Hd, nullptr, nullptr,
                              p.W_out, 0, tile * 64, Cc, As, Wsm, tid, vals);
            #pragma unroll
            for (int i = 0; i < 4; i++)
                #pragma unroll
                for (int j = 0; j < 4; j++) {
                    const int ng = tile * 64 + c + 16 * j;
                    if (ng < Cc)
                        p.out[(size_t)(mt + i) * Cc + ng] = vals[i][j] + __ldg(&p.b_out[ng]);
                }
        }
    }

    // exit handshake: last CTA resets all sync state for the next graph replay
    __threadfence();
    __syncthreads();
    if (tid == 0) {
        unsigned prev = atomicAdd(&g_exit_cnt, 1u);
        if (prev == GRID - 1u) {
            for (int i = 0; i < 96; i++) g_tile_ctr[i] = 0u;
            g_exit_cnt = 0u;
            g_bar_cnt  = 0u;
            g_bar_gen  = 0u;
            __threadfence();
        }
    }
}

extern "C" void kernel_launch(void* const* d_in, const int* in_sizes, int n_in,
                              void* d_out, int out_size) {
    (void)in_sizes; (void)n_in; (void)out_size;
    PArgs p;
    p.wv      = (const float*)d_in[0];
    p.h       = (const float*)d_in[1];
    p.bi      = (const int*)  d_in[2];
    p.W0      = (const float*)d_in[3];
    p.b0      = (const float*)d_in[4];
    p.Ws      = (const float*)d_in[5];
    p.bs      = (const float*)d_in[6];
    p.W_out   = (const float*)d_in[7];
    p.b_out   = (const float*)d_in[8];
    p.W_sum   = (const float*)d_in[9];
    p.b_sum   = (const float*)d_in[10];
    p.actions = (const float*)d_in[11];
    p.out     = (float*)d_out;

    rnn_persistent<<<GRID, 256>>>(p);
}

// round 10
// speedup vs baseline: 4.5740x; 1.4395x over previous
#include <cuda_runtime.h>
#include <cuda_bf16.h>
#include <math.h>
#include <stdint.h>

#define Bq 64
#define Hd 1024
#define Tt 128
#define NSTEP 127
#define Cc 50000
#define GRID 256
#define TM 64
#define TN 64
#define KCH 32
#define AST 36     // fp32 final-gemm A smem stride
#define WST 34     // fp32 final-gemm W smem stride
#define SMEMB (4 * 64 * 136 * 2)   // 69,632 B dynamic smem (bf16 hi/lo A+W tiles, KPER=128)

// Scratch (no cudaMalloc allowed)
__device__ float g_h[2][Bq * Hd];
__device__ float g_out1[Bq * Hd];
__device__ float g_out23[Bq * 2 * Hd];
__device__ float g_out45[Bq * 2 * Hd];
__device__ float g_part[256 * 4096];
__device__ float g_c[3];
__device__ unsigned g_tile_ctr[96];
__device__ unsigned g_bar_cnt;
__device__ volatile unsigned g_bar_gen;
__device__ unsigned g_exit_cnt;
// Pre-split recurrent weights: rows 0-6143 = Ws[0..5], rows 6144-7167 = W0. [row][1024] bf16.
__device__ __nv_bfloat16 g_Whi[7 * 1024 * 1024];
__device__ __nv_bfloat16 g_Wlo[7 * 1024 * 1024];

struct PArgs {
    const float* wv; const float* h; const int* bi;
    const float* W0; const float* b0;
    const float* Ws; const float* bs;
    const float* W_out; const float* b_out;
    const float* W_sum; const float* b_sum; const float* actions;
    float* out;
};

// ---------- small helpers ----------
__device__ __forceinline__ unsigned long long ffma2(unsigned long long a,
                                                    unsigned long long b,
                                                    unsigned long long c) {
    unsigned long long d;
    asm("fma.rn.f32x2 %0, %1, %2, %3;" : "=l"(d) : "l"(a), "l"(b), "l"(c));
    return d;
}
__device__ __forceinline__ float unpack_sum(unsigned long long p) {
    float lo, hi;
    asm("mov.b64 {%0, %1}, %2;" : "=f"(lo), "=f"(hi) : "l"(p));
    return lo + hi;
}
__device__ __forceinline__ uint32_t su32(const void* p) {
    return (uint32_t)__cvta_generic_to_shared(p);
}
__device__ __forceinline__ void ldsm4(uint32_t* r, uint32_t addr) {
    asm volatile("ldmatrix.sync.aligned.m8n8.x4.shared.b16 {%0,%1,%2,%3}, [%4];"
                 : "=r"(r[0]), "=r"(r[1]), "=r"(r[2]), "=r"(r[3]) : "r"(addr));
}
__device__ __forceinline__ void mma_bf16(float* d, const uint32_t* a, uint32_t b0, uint32_t b1) {
    asm volatile("mma.sync.aligned.m16n8k16.row.col.f32.bf16.bf16.f32 "
                 "{%0,%1,%2,%3}, {%4,%5,%6,%7}, {%8,%9}, {%0,%1,%2,%3};"
                 : "+f"(d[0]), "+f"(d[1]), "+f"(d[2]), "+f"(d[3])
                 : "r"(a[0]), "r"(a[1]), "r"(a[2]), "r"(a[3]), "r"(b0), "r"(b1));
}
// split fp32x4 -> bf16 hi/lo and store 4 elems to each smem/gmem target
__device__ __forceinline__ void split4(__nv_bfloat16* hi, __nv_bfloat16* lo, float4 v) {
    __nv_bfloat16 h0 = __float2bfloat16_rn(v.x), h1 = __float2bfloat16_rn(v.y);
    __nv_bfloat16 h2 = __float2bfloat16_rn(v.z), h3 = __float2bfloat16_rn(v.w);
    __nv_bfloat16 l0 = __float2bfloat16_rn(v.x - __bfloat162float(h0));
    __nv_bfloat16 l1 = __float2bfloat16_rn(v.y - __bfloat162float(h1));
    __nv_bfloat16 l2 = __float2bfloat16_rn(v.z - __bfloat162float(h2));
    __nv_bfloat16 l3 = __float2bfloat16_rn(v.w - __bfloat162float(h3));
    __nv_bfloat162 a; a.x = h0; a.y = h1; *(__nv_bfloat162*)(hi)     = a;
    __nv_bfloat162 b; b.x = h2; b.y = h3; *(__nv_bfloat162*)(hi + 2) = b;
    __nv_bfloat162 c; c.x = l0; c.y = l1; *(__nv_bfloat162*)(lo)     = c;
    __nv_bfloat162 d; d.x = l2; d.y = l3; *(__nv_bfloat162*)(lo + 2) = d;
}

// ---------- grid/group sync ----------
__device__ __forceinline__ void grid_barrier(unsigned target) {
    __syncthreads();
    if (threadIdx.x == 0) {
        __threadfence();
        unsigned prev = atomicAdd(&g_bar_cnt, 1u);
        if (prev == GRID - 1u) {
            g_bar_cnt = 0u;
            __threadfence();
            g_bar_gen = target;
        } else {
            while (g_bar_gen < target) __nanosleep(32);
        }
        __threadfence();
    }
    __syncthreads();
}
__device__ __forceinline__ void group_sync(unsigned* ctr, unsigned target) {
    __syncthreads();
    if (threadIdx.x == 0) {
        __threadfence();
        atomicAdd(ctr, 1u);
        while (*(volatile unsigned*)ctr < target) __nanosleep(32);
        __threadfence();
    }
    __syncthreads();
}

// ---------- bf16x3 MMA gemm: acc[4][4] += A[64,KPER] @ W[64,KPER]^T ----------
// Whi/Wlo: pre-offset to (row n0, col kbase), row stride 1024.
template<int KPER, bool GATHER>
__device__ __forceinline__ void gemm_mma(
    const float* A, int lda, int kbase,
    const float* wv, const int* idx,
    const __nv_bfloat16* Whi, const __nv_bfloat16* Wlo,
    char* smem, int tid, float acc[4][4])
{
    constexpr int AS = KPER + 8;           // bf16 row stride: 8-row bank-distinct for ldmatrix
    __nv_bfloat16* sAhi = (__nv_bfloat16*)smem;
    __nv_bfloat16* sAlo = sAhi + 64 * AS;
    __nv_bfloat16* sWhi = sAlo + 64 * AS;
    __nv_bfloat16* sWlo = sWhi + 64 * AS;

    // Stage A: load fp32, split to hi/lo bf16
    {
        const int r0 = tid >> 3;
        const int kf = (tid & 7) * 4;
        #pragma unroll
        for (int rr = 0; rr < 2; rr++) {
            const int r = r0 + rr * 32;
            const float* arow;
            if (GATHER) arow = wv + (size_t)__ldg(idx + r * Tt) * Hd;
            else        arow = A + (size_t)r * lda;
            #pragma unroll
            for (int c = 0; c < KPER / 32; c++) {
                const int k = kf + 32 * c;
                float4 v = GATHER ? __ldg((const float4*)(arow + kbase + k))
                                  : __ldcg((const float4*)(arow + kbase + k));
                split4(&sAhi[r * AS + k], &sAlo[r * AS + k], v);
            }
        }
    }
    // Stage W: copy pre-split bf16 rows
    {
        const int r0 = tid >> 3;
        const int t8 = tid & 7;
        #pragma unroll
        for (int rr = 0; rr < 2; rr++) {
            const int r = r0 + rr * 32;
            const __nv_bfloat16* sh = Whi + (size_t)r * Hd;
            const __nv_bfloat16* sl = Wlo + (size_t)r * Hd;
            if (KPER == 128) {
                const int k = t8 * 16;
                *(uint4*)&sWhi[r * AS + k]     = __ldg((const uint4*)(sh + k));
                *(uint4*)&sWhi[r * AS + k + 8] = __ldg((const uint4*)(sh + k + 8));
                *(uint4*)&sWlo[r * AS + k]     = __ldg((const uint4*)(sl + k));
                *(uint4*)&sWlo[r * AS + k + 8] = __ldg((const uint4*)(sl + k + 8));
            } else {   // KPER == 64
                const int k = t8 * 8;
                *(uint4*)&sWhi[r * AS + k] = __ldg((const uint4*)(sh + k));
                *(uint4*)&sWlo[r * AS + k] = __ldg((const uint4*)(sl + k));
            }
        }
    }
    __syncthreads();

    const int lane = tid & 31;
    const int w    = tid >> 5;
    const int rw = (w >> 1) * 16;          // warp row block (0..48)
    const int cw = (w & 1) * 32;           // warp col block (0 or 32)
    const int rr8 = lane & 7;
    // ldmatrix per-lane source rows/cols (see m16n8k16 fragment layouts)
    const int aRow = rw + rr8 + (((lane >> 3) & 1) ? 8 : 0);
    const int aCol = ((lane >> 4) & 1) ? 8 : 0;
    const int bRow = cw + rr8 + (((lane >> 4) & 1) ? 8 : 0);
    const int bCol = ((lane >> 3) & 1) ? 8 : 0;

    const uint32_t aHi = su32(&sAhi[aRow * AS + aCol]);
    const uint32_t aLo = su32(&sAlo[aRow * AS + aCol]);
    const uint32_t bHi0 = su32(&sWhi[bRow * AS + bCol]);
    const uint32_t bHi1 = su32(&sWhi[(bRow + 16) * AS + bCol]);
    const uint32_t bLo0 = su32(&sWlo[bRow * AS + bCol]);
    const uint32_t bLo1 = su32(&sWlo[(bRow + 16) * AS + bCol]);

    #pragma unroll
    for (int k16 = 0; k16 < KPER / 16; k16++) {
        const uint32_t ko = k16 * 32;      // 16 bf16 = 32 bytes
        uint32_t ah[4], al[4], bh[8], bl[8];
        ldsm4(ah, aHi + ko);
        ldsm4(al, aLo + ko);
        ldsm4(bh,     bHi0 + ko);
        ldsm4(bh + 4, bHi1 + ko);
        ldsm4(bl,     bLo0 + ko);
        ldsm4(bl + 4, bLo1 + ko);
        #pragma unroll
        for (int nb = 0; nb < 4; nb++) {
            mma_bf16(acc[nb], ah, bh[nb * 2], bh[nb * 2 + 1]);   // hi*hi
            mma_bf16(acc[nb], ah, bl[nb * 2], bl[nb * 2 + 1]);   // hi*lo
            mma_bf16(acc[nb], al, bh[nb * 2], bh[nb * 2 + 1]);   // lo*hi
        }
    }
}

__device__ __forceinline__ void store_partial_mma(int slot, int tid, const float acc[4][4]) {
    float* p = &g_part[(size_t)slot * 4096];
    const int lane = tid & 31, w = tid >> 5;
    const int rw = (w >> 1) * 16, cw = (w & 1) * 32;
    const int grp = lane >> 2, tig = lane & 3;
    float* pr = p + (rw + grp) * 64 + cw + 2 * tig;
    #pragma unroll
    for (int nb = 0; nb < 4; nb++) {
        __stcg((float2*)(pr + nb * 8),          make_float2(acc[nb][0], acc[nb][1]));
        __stcg((float2*)(pr + 8 * 64 + nb * 8), make_float2(acc[nb][2], acc[nb][3]));
    }
}

// ---------- group reduce + activation ----------
template<int NSPLIT>
__device__ __forceinline__ void group_reduce(
    int tile, int s, int tid, const float* bias, const float* bias2,
    int mode, float* out, int ldo, const float* e1, const float* e2)
{
    const int per = 4096 / NSPLIT;
    const float* pt = &g_part[(size_t)(tile * NSPLIT) * 4096];
    #pragma unroll 2
    for (int i = tid; i < per; i += 256) {
        const int local = s * per + i;
        float v = 0.f;
        #pragma unroll
        for (int ss = 0; ss < NSPLIT; ss++) v += __ldcg(pt + ss * 4096 + local);
        const int m  = local >> 6;
        const int ng = tile * 64 + (local & 63);
        v += __ldg(&bias[ng]);
        if (bias2) v += __ldg(&bias2[ng]);
        float r;
        switch (mode) {
            case 0: r = tanhf(v); break;
            case 1: r = (ng < Hd) ? fmaxf(v, 0.f) : (1.f / (1.f + expf(-v))); break;
            case 2: r = (ng < Hd) ? tanhf(v) : fmaxf(v, 0.f); break;
            default:
                r = g_c[2] * tanhf(v)
                  + g_c[0] * __ldcg(&e1[(size_t)m * 2 * Hd + ng])
                  + g_c[1] * __ldcg(&e2[(size_t)m * 2 * Hd + ng]);
        }
        __stcg(&out[(size_t)m * ldo + ng], r);
    }
}

// ---------- fp32 FFMA2 gemm (final DRAM-bound GEMM only) ----------
template<int KPER>
__device__ __forceinline__ void gemm64_f32(
    const float* A, int lda, const float* Wp, int n0, int Nlim,
    float (*As)[TM][AST], float (*Wsm)[TN][WST], int tid, float vals[4][4])
{
    const int mr0 = tid >> 3, mr1 = mr0 + 32;
    const int kf  = (tid & 7) * 4;
    const float* arow0 = A + (size_t)mr0 * lda + kf;
    const float* arow1 = A + (size_t)mr1 * lda + kf;
    const bool wok0 = (n0 + mr0) < Nlim;
    const bool wok1 = (n0 + mr1) < Nlim;
    const float* wrow0 = Wp + (size_t)(n0 + mr0) * Hd + kf;
    const float* wrow1 = Wp + (size_t)(n0 + mr1) * Hd + kf;

    const int r  = tid >> 4;
    const int c  = tid & 15;
    const int mt = r * 4;

    unsigned long long acc[4][4];
    #pragma unroll
    for (int i = 0; i < 4; i++)
        #pragma unroll
        for (int j = 0; j < 4; j++) acc[i][j] = 0ull;

    const int nch = KPER / KCH;
    const float4 z4 = make_float4(0.f, 0.f, 0.f, 0.f);

    float4 va0 = __ldcg((const float4*)(arow0));
    float4 va1 = __ldcg((const float4*)(arow1));
    float4 vw0 = wok0 ? __ldg((const float4*)(wrow0)) : z4;
    float4 vw1 = wok1 ? __ldg((const float4*)(wrow1)) : z4;
    *(float4*)&As[0][mr0][kf] = va0;
    *(float4*)&As[0][mr1][kf] = va1;
    *(float2*)&Wsm[0][mr0][kf]     = make_float2(vw0.x, vw0.y);
    *(float2*)&Wsm[0][mr0][kf + 2] = make_float2(vw0.z, vw0.w);
    *(float2*)&Wsm[0][mr1][kf]     = make_float2(vw1.x, vw1.y);
    *(float2*)&Wsm[0][mr1][kf + 2] = make_float2(vw1.z, vw1.w);
    __syncthreads();

    for (int ch = 0; ch < nch; ch++) {
        const int b = ch & 1;
        const bool more = (ch + 1) < nch;
        if (more) {
            const int o = (ch + 1) * KCH;
            va0 = __ldcg((const float4*)(arow0 + o));
            va1 = __ldcg((const float4*)(arow1 + o));
            vw0 = wok0 ? __ldg((const float4*)(wrow0 + o)) : z4;
            vw1 = wok1 ? __ldg((const float4*)(wrow1 + o)) : z4;
        }
        #pragma unroll
        for (int k4 = 0; k4 < KCH / 4; k4++) {
            ulonglong2 a[4];
            #pragma unroll
            for (int i = 0; i < 4; i++)
                a[i] = *(const ulonglong2*)&As[b][mt + i][k4 * 4];
            #pragma unroll
            for (int j = 0; j < 4; j++) {
                const int n = c + 16 * j;
                unsigned long long wlo = *(const unsigned long long*)&Wsm[b][n][k4 * 4];
                unsigned long long whi = *(const unsigned long long*)&Wsm[b][n][k4 * 4 + 2];
                #pragma unroll
                for (int i = 0; i < 4; i++) {
                    acc[i][j] = ffma2(a[i].x, wlo, acc[i][j]);
                    acc[i][j] = ffma2(a[i].y, whi, acc[i][j]);
                }
            }
        }
        if (more) {
            const int nb = (ch + 1) & 1;
            *(float4*)&As[nb][mr0][kf] = va0;
            *(float4*)&As[nb][mr1][kf] = va1;
            *(float2*)&Wsm[nb][mr0][kf]     = make_float2(vw0.x, vw0.y);
            *(float2*)&Wsm[nb][mr0][kf + 2] = make_float2(vw0.z, vw0.w);
            *(float2*)&Wsm[nb][mr1][kf]     = make_float2(vw1.x, vw1.y);
            *(float2*)&Wsm[nb][mr1][kf + 2] = make_float2(vw1.z, vw1.w);
        }
        __syncthreads();
    }

    #pragma unroll
    for (int i = 0; i < 4; i++)
        #pragma unroll
        for (int j = 0; j < 4; j++) vals[i][j] = unpack_sum(acc[i][j]);
}

// ---------- persistent kernel ----------
__global__ void __launch_bounds__(256, 2) rnn_persistent(PArgs p) {
    extern __shared__ __align__(16) char smem[];

    const int bid = blockIdx.x;
    const int tid = threadIdx.x;

    if (bid == 0 && tid == 0) {
        const int rows[3] = {1, 3, 5};
        float wgt[3];
        for (int i = 0; i < 3; i++) {
            float acc = p.b_sum[rows[i]];
            for (int j = 0; j < 12; j++) acc += p.W_sum[rows[i] * 12 + j] * p.actions[j];
            wgt[i] = acc;
        }
        float mx = fmaxf(wgt[0], fmaxf(wgt[1], wgt[2]));
        float e0 = expf(wgt[0] - mx), e1 = expf(wgt[1] - mx), e2 = expf(wgt[2] - mx);
        float s = e0 + e1 + e2;
        g_c[0] = e0 / s; g_c[1] = e1 / s; g_c[2] = e2 / s;
    }

    unsigned bar = 0;

    // Pre-split recurrent weights (Ws then W0) into bf16 hi/lo, once per launch.
    {
        const int gtid = bid * 256 + tid;
        const int total4 = 7 * 1024 * 1024 / 4;       // 1,835,008 float4s
        const int ws4    = 6 * 1024 * 1024 / 4;
        for (int i = gtid; i < total4; i += GRID * 256) {
            float4 v = (i < ws4) ? __ldg((const float4*)p.Ws + i)
                                 : __ldg((const float4*)p.W0 + (i - ws4));
            split4(&g_Whi[(size_t)i * 4], &g_Wlo[(size_t)i * 4], v);
        }
    }
    grid_barrier(++bar);

    float* gh0 = g_h[0];
    float* gh1 = g_h[1];
    const int tile16 = bid >> 4, s16 = bid & 15;
    const int tile8  = bid >> 3, s8  = bid & 7;

    for (int t = 0; t < NSTEP; t++) {
        const float* hin  = (t == 0) ? p.h : ((t & 1) ? gh1 : gh0);
        float*       hout = ((t + 1) & 1) ? gh1 : gh0;

        // phase 1: out1 = tanh(h @ Ws0^T + wv[idx] @ W0^T + bs0 + b0)  (virtual K=2048, nsplit=16)
        {
            float acc[4][4] = {};
            if (s16 < 8) {
                const size_t wo = (size_t)(tile16 * 64) * Hd + s16 * 128;
                gemm_mma<128, false>(hin, Hd, s16 * 128, nullptr, nullptr,
                                     g_Whi + wo, g_Wlo + wo, smem, tid, acc);
            } else {
                const size_t wo = (size_t)(6 * 1024 + tile16 * 64) * Hd + (s16 - 8) * 128;
                gemm_mma<128, true>(nullptr, 0, (s16 - 8) * 128, p.wv, p.bi + (t + 1),
                                    g_Whi + wo, g_Wlo + wo, smem, tid, acc);
            }
            store_partial_mma(bid, tid, acc);
        }
        group_sync(&g_tile_ctr[tile16], (unsigned)(t + 1) * 16u);
        group_reduce<16>(tile16, s16, tid, p.bs, p.b0, 0, g_out1, Hd, nullptr, nullptr);
        grid_barrier(++bar);

        // phase 2: [out2|out3] = [relu|sigmoid](out1 @ [Ws1;Ws2]^T + [bs1;bs2])  (nsplit=8)
        {
            float acc[4][4] = {};
            const size_t wo = (size_t)(1024 + tile8 * 64) * Hd + s8 * 128;
            gemm_mma<128, false>(g_out1, Hd, s8 * 128, nullptr, nullptr,
                                 g_Whi + wo, g_Wlo + wo, smem, tid, acc);
            store_partial_mma(bid, tid, acc);
        }
        group_sync(&g_tile_ctr[16 + tile8], (unsigned)(t + 1) * 8u);
        group_reduce<8>(tile8, s8, tid, p.bs + Hd, nullptr, 1, g_out23, 2 * Hd, nullptr, nullptr);
        grid_barrier(++bar);

        // phase 3: [out4|out5] = [tanh|relu](out3 @ [Ws3;Ws4]^T + [bs3;bs4])  (nsplit=8)
        {
            float acc[4][4] = {};
            const size_t wo = (size_t)(3 * 1024 + tile8 * 64) * Hd + s8 * 128;
            gemm_mma<128, false>(g_out23 + Hd, 2 * Hd, s8 * 128, nullptr, nullptr,
                                 g_Whi + wo, g_Wlo + wo, smem, tid, acc);
            store_partial_mma(bid, tid, acc);
        }
        group_sync(&g_tile_ctr[48 + tile8], (unsigned)(t + 1) * 8u);
        group_reduce<8>(tile8, s8, tid, p.bs + 3 * Hd, nullptr, 2, g_out45, 2 * Hd, nullptr, nullptr);
        grid_barrier(++bar);

        // phase 4: h_new = c2*tanh(out5 @ Ws5^T + bs5) + c0*out2 + c1*out4  (nsplit=16, KPER=64)
        {
            float acc[4][4] = {};
            const size_t wo = (size_t)(5 * 1024 + tile16 * 64) * Hd + s16 * 64;
            gemm_mma<64, false>(g_out45 + Hd, 2 * Hd, s16 * 64, nullptr, nullptr,
                                g_Whi + wo, g_Wlo + wo, smem, tid, acc);
            store_partial_mma(bid, tid, acc);
        }
        group_sync(&g_tile_ctr[80 + tile16], (unsigned)(t + 1) * 16u);
        group_reduce<16>(tile16, s16, tid, p.bs + 5 * Hd, nullptr, 3, hout, Hd, g_out23, g_out45);
        grid_barrier(++bar);
    }

    // final: logits = h_final @ W_out^T + b_out  [64, 50000]  (fp32, DRAM-bound)
    {
        float (*As)[TM][AST]  = (float (*)[TM][AST])smem;
        float (*Wsm)[TN][WST] = (float (*)[TN][WST])(smem + 2 * TM * AST * 4);
        const float* hf = gh1;   // (126+1)&1 == 1
        const int ntiles = (Cc + TN - 1) / TN;
        const int mt = (tid >> 4) * 4;
        const int c  = tid & 15;
        float vals[4][4];
        for (int tile = bid; tile < ntiles; tile += GRID) {
            gemm64_f32<Hd>(hf, Hd, p.W_out, tile * 64, Cc, As, Wsm, tid, vals);
            #pragma unroll
            for (int i = 0; i < 4; i++)
                #pragma unroll
                for (int j = 0; j < 4; j++) {
                    const int ng = tile * 64 + c + 16 * j;
                    if (ng < Cc)
                        p.out[(size_t)(mt + i) * Cc + ng] = vals[i][j] + __ldg(&p.b_out[ng]);
                }
        }
    }

    // exit handshake: last CTA resets all sync state for the next graph replay
    __threadfence();
    __syncthreads();
    if (tid == 0) {
        unsigned prev = atomicAdd(&g_exit_cnt, 1u);
        if (prev == GRID - 1u) {
            for (int i = 0; i < 96; i++) g_tile_ctr[i] = 0u;
            g_exit_cnt = 0u;
            g_bar_cnt  = 0u;
            g_bar_gen  = 0u;
            __threadfence();
        }
    }
}

extern "C" void kernel_launch(void* const* d_in, const int* in_sizes, int n_in,
                              void* d_out, int out_size) {
    (void)in_sizes; (void)n_in; (void)out_size;
    PArgs p;
    p.wv      = (const float*)d_in[0];
    p.h       = (const float*)d_in[1];
    p.bi      = (const int*)  d_in[2];
    p.W0      = (const float*)d_in[3];
    p.b0      = (const float*)d_in[4];
    p.Ws      = (const float*)d_in[5];
    p.bs      = (const float*)d_in[6];
    p.W_out   = (const float*)d_in[7];
    p.b_out   = (const float*)d_in[8];
    p.W_sum   = (const float*)d_in[9];
    p.b_sum   = (const float*)d_in[10];
    p.actions = (const float*)d_in[11];
    p.out     = (float*)d_out;

    cudaFuncSetAttribute(rnn_persistent, cudaFuncAttributeMaxDynamicSharedMemorySize, SMEMB);
    cudaFuncSetAttribute(rnn_persistent, cudaFuncAttributePreferredSharedMemoryCarveout, 100);
    rnn_persistent<<<GRID, 256, SMEMB>>>(p);
}

// round 11
// speedup vs baseline: 4.7241x; 1.0328x over previous
#include <cuda_runtime.h>
#include <cuda_bf16.h>
#include <math.h>
#include <stdint.h>

#define Bq 64
#define Hd 1024
#define Tt 128
#define NSTEP 127
#define Cc 50000
#define GRID 256
#define TM 64
#define TN 64
#define KCH 32
#define ASf 36     // fp32 final-gemm A smem stride
#define WSf 34     // fp32 final-gemm W smem stride
#define AS 136     // bf16 smem row stride (all phases)
#define SMEMB (4 * 64 * AS * 2)    // 69,632 B

// Scratch (no cudaMalloc allowed)
__device__ float g_h[2][Bq * Hd];
__device__ float g_out1[Bq * Hd];
__device__ float g_out23[Bq * 2 * Hd];
__device__ float g_out45[Bq * 2 * Hd];
__device__ float g_part[256 * 4096];
__device__ float g_c[3];
__device__ unsigned g_tile_ctr[96];
__device__ unsigned g_bar_cnt;
__device__ volatile unsigned g_bar_gen;
__device__ unsigned g_exit_cnt;
// Pre-split recurrent weights: rows 0-6143 = Ws[0..5], rows 6144-7167 = W0. [row][1024] bf16.
__device__ __nv_bfloat16 g_Whi[7 * 1024 * 1024];
__device__ __nv_bfloat16 g_Wlo[7 * 1024 * 1024];

struct PArgs {
    const float* wv; const float* h; const int* bi;
    const float* W0; const float* b0;
    const float* Ws; const float* bs;
    const float* W_out; const float* b_out;
    const float* W_sum; const float* b_sum; const float* actions;
    float* out;
};

// ---------- helpers ----------
__device__ __forceinline__ unsigned long long ffma2(unsigned long long a,
                                                    unsigned long long b,
                                                    unsigned long long c) {
    unsigned long long d;
    asm("fma.rn.f32x2 %0, %1, %2, %3;" : "=l"(d) : "l"(a), "l"(b), "l"(c));
    return d;
}
__device__ __forceinline__ float unpack_sum(unsigned long long p) {
    float lo, hi;
    asm("mov.b64 {%0, %1}, %2;" : "=f"(lo), "=f"(hi) : "l"(p));
    return lo + hi;
}
__device__ __forceinline__ uint32_t su32(const void* p) {
    return (uint32_t)__cvta_generic_to_shared(p);
}
__device__ __forceinline__ void cp16(uint32_t saddr, const void* g) {
    asm volatile("cp.async.cg.shared.global [%0], [%1], 16;" :: "r"(saddr), "l"(g));
}
__device__ __forceinline__ void cp_commit() { asm volatile("cp.async.commit_group;"); }
__device__ __forceinline__ void cp_wait0()  { asm volatile("cp.async.wait_group 0;"); }
__device__ __forceinline__ void ldsm4(uint32_t* r, uint32_t addr) {
    asm volatile("ldmatrix.sync.aligned.m8n8.x4.shared.b16 {%0,%1,%2,%3}, [%4];"
                 : "=r"(r[0]), "=r"(r[1]), "=r"(r[2]), "=r"(r[3]) : "r"(addr));
}
__device__ __forceinline__ void mma_bf16(float* d, const uint32_t* a, uint32_t b0, uint32_t b1) {
    asm volatile("mma.sync.aligned.m16n8k16.row.col.f32.bf16.bf16.f32 "
                 "{%0,%1,%2,%3}, {%4,%5,%6,%7}, {%8,%9}, {%0,%1,%2,%3};"
                 : "+f"(d[0]), "+f"(d[1]), "+f"(d[2]), "+f"(d[3])
                 : "r"(a[0]), "r"(a[1]), "r"(a[2]), "r"(a[3]), "r"(b0), "r"(b1));
}
__device__ __forceinline__ void split4(__nv_bfloat16* hi, __nv_bfloat16* lo, float4 v) {
    __nv_bfloat16 h0 = __float2bfloat16_rn(v.x), h1 = __float2bfloat16_rn(v.y);
    __nv_bfloat16 h2 = __float2bfloat16_rn(v.z), h3 = __float2bfloat16_rn(v.w);
    __nv_bfloat16 l0 = __float2bfloat16_rn(v.x - __bfloat162float(h0));
    __nv_bfloat16 l1 = __float2bfloat16_rn(v.y - __bfloat162float(h1));
    __nv_bfloat16 l2 = __float2bfloat16_rn(v.z - __bfloat162float(h2));
    __nv_bfloat16 l3 = __float2bfloat16_rn(v.w - __bfloat162float(h3));
    __nv_bfloat162 a; a.x = h0; a.y = h1; *(__nv_bfloat162*)(hi)     = a;
    __nv_bfloat162 b; b.x = h2; b.y = h3; *(__nv_bfloat162*)(hi + 2) = b;
    __nv_bfloat162 c; c.x = l0; c.y = l1; *(__nv_bfloat162*)(lo)     = c;
    __nv_bfloat162 d; d.x = l2; d.y = l3; *(__nv_bfloat162*)(lo + 2) = d;
}

// ---------- sync ----------
__device__ __forceinline__ void grid_barrier(unsigned target) {
    __syncthreads();
    if (threadIdx.x == 0) {
        __threadfence();
        unsigned prev = atomicAdd(&g_bar_cnt, 1u);
        if (prev == GRID - 1u) {
            g_bar_cnt = 0u;
            __threadfence();
            g_bar_gen = target;
        } else {
            while (g_bar_gen < target) { }
        }
        __threadfence();
    }
    __syncthreads();
}
__device__ __forceinline__ void group_sync(unsigned* ctr, unsigned target) {
    __syncthreads();
    if (threadIdx.x == 0) {
        __threadfence();
        atomicAdd(ctr, 1u);
        while (*(volatile unsigned*)ctr < target) { }
        __threadfence();
    }
    __syncthreads();
}

// ---------- smem region accessors (bf16) ----------
__device__ __forceinline__ __nv_bfloat16* sm_Ahi(char* s) { return (__nv_bfloat16*)s; }
__device__ __forceinline__ __nv_bfloat16* sm_Alo(char* s) { return (__nv_bfloat16*)s + 64 * AS; }
__device__ __forceinline__ __nv_bfloat16* sm_Whi(char* s) { return (__nv_bfloat16*)s + 2 * 64 * AS; }
__device__ __forceinline__ __nv_bfloat16* sm_Wlo(char* s) { return (__nv_bfloat16*)s + 3 * 64 * AS; }

// Async W stage: pre-split bf16 rows -> smem via cp.async (completion via cp_wait0 later).
template<int KPER>
__device__ __forceinline__ void stage_W_async(
    const __nv_bfloat16* Whi, const __nv_bfloat16* Wlo, char* smem, int tid)
{
    __nv_bfloat16* sWhi = sm_Whi(smem);
    __nv_bfloat16* sWlo = sm_Wlo(smem);
    const int r0 = tid >> 3;
    const int t8 = tid & 7;
    #pragma unroll
    for (int rr = 0; rr < 2; rr++) {
        const int r = r0 + rr * 32;
        const __nv_bfloat16* sh = Whi + (size_t)r * Hd;
        const __nv_bfloat16* sl = Wlo + (size_t)r * Hd;
        if (KPER == 128) {
            const int k = t8 * 16;
            cp16(su32(&sWhi[r * AS + k]),     sh + k);
            cp16(su32(&sWhi[r * AS + k + 8]), sh + k + 8);
            cp16(su32(&sWlo[r * AS + k]),     sl + k);
            cp16(su32(&sWlo[r * AS + k + 8]), sl + k + 8);
        } else {   // KPER == 64
            const int k = t8 * 8;
            cp16(su32(&sWhi[r * AS + k]), sh + k);
            cp16(su32(&sWlo[r * AS + k]), sl + k);
        }
    }
    cp_commit();
}

// Stage A: load fp32, split to hi/lo bf16 in smem.
template<int KPER, bool GATHER>
__device__ __forceinline__ void stage_A(
    const float* A, int lda, int kbase,
    const float* wv, const int* idx, char* smem, int tid)
{
    __nv_bfloat16* sAhi = sm_Ahi(smem);
    __nv_bfloat16* sAlo = sm_Alo(smem);
    const int r0 = tid >> 3;
    const int kf = (tid & 7) * 4;
    #pragma unroll
    for (int rr = 0; rr < 2; rr++) {
        const int r = r0 + rr * 32;
        const float* arow;
        if (GATHER) arow = wv + (size_t)__ldg(idx + r * Tt) * Hd;
        else        arow = A + (size_t)r * lda;
        #pragma unroll
        for (int c = 0; c < KPER / 32; c++) {
            const int k = kf + 32 * c;
            float4 v = GATHER ? __ldg((const float4*)(arow + kbase + k))
                              : __ldcg((const float4*)(arow + kbase + k));
            split4(&sAhi[r * AS + k], &sAlo[r * AS + k], v);
        }
    }
}

// MMA compute on staged smem: acc += A @ W^T (bf16x3).
template<int KPER>
__device__ __forceinline__ void compute_mma(char* smem, int tid, float acc[4][4]) {
    __nv_bfloat16* sAhi = sm_Ahi(smem);
    __nv_bfloat16* sAlo = sm_Alo(smem);
    __nv_bfloat16* sWhi = sm_Whi(smem);
    __nv_bfloat16* sWlo = sm_Wlo(smem);

    const int lane = tid & 31;
    const int w    = tid >> 5;
    const int rw = (w >> 1) * 16;
    const int cw = (w & 1) * 32;
    const int rr8 = lane & 7;
    const int aRow = rw + rr8 + (((lane >> 3) & 1) ? 8 : 0);
    const int aCol = ((lane >> 4) & 1) ? 8 : 0;
    const int bRow = cw + rr8 + (((lane >> 4) & 1) ? 8 : 0);
    const int bCol = ((lane >> 3) & 1) ? 8 : 0;

    const uint32_t aHi = su32(&sAhi[aRow * AS + aCol]);
    const uint32_t aLo = su32(&sAlo[aRow * AS + aCol]);
    const uint32_t bHi0 = su32(&sWhi[bRow * AS + bCol]);
    const uint32_t bHi1 = su32(&sWhi[(bRow + 16) * AS + bCol]);
    const uint32_t bLo0 = su32(&sWlo[bRow * AS + bCol]);
    const uint32_t bLo1 = su32(&sWlo[(bRow + 16) * AS + bCol]);

    #pragma unroll
    for (int k16 = 0; k16 < KPER / 16; k16++) {
        const uint32_t ko = k16 * 32;
        uint32_t ah[4], al[4], bh[8], bl[8];
        ldsm4(ah, aHi + ko);
        ldsm4(al, aLo + ko);
        ldsm4(bh,     bHi0 + ko);
        ldsm4(bh + 4, bHi1 + ko);
        ldsm4(bl,     bLo0 + ko);
        ldsm4(bl + 4, bLo1 + ko);
        #pragma unroll
        for (int nb = 0; nb < 4; nb++) {
            mma_bf16(acc[nb], ah, bh[nb * 2], bh[nb * 2 + 1]);
            mma_bf16(acc[nb], ah, bl[nb * 2], bl[nb * 2 + 1]);
            mma_bf16(acc[nb], al, bh[nb * 2], bh[nb * 2 + 1]);
        }
    }
}

__device__ __forceinline__ void store_partial_mma(int slot, int tid, const float acc[4][4]) {
    float* p = &g_part[(size_t)slot * 4096];
    const int lane = tid & 31, w = tid >> 5;
    const int rw = (w >> 1) * 16, cw = (w & 1) * 32;
    const int grp = lane >> 2, tig = lane & 3;
    float* pr = p + (rw + grp) * 64 + cw + 2 * tig;
    #pragma unroll
    for (int nb = 0; nb < 4; nb++) {
        __stcg((float2*)(pr + nb * 8),          make_float2(acc[nb][0], acc[nb][1]));
        __stcg((float2*)(pr + 8 * 64 + nb * 8), make_float2(acc[nb][2], acc[nb][3]));
    }
}

// ---------- group reduce + activation (float4) ----------
template<int NSPLIT>
__device__ __forceinline__ void group_reduce(
    int tile, int s, int tid, const float* bias, const float* bias2,
    int mode, float* out, int ldo, const float* e1, const float* e2)
{
    const int per4 = 4096 / NSPLIT / 4;    // 64 (nsplit16) or 128 (nsplit8)
    const float4* pt = (const float4*)&g_part[(size_t)(tile * NSPLIT) * 4096];
    for (int i4 = tid; i4 < per4; i4 += 256) {
        const int local4 = s * per4 + i4;
        float4 v = make_float4(0.f, 0.f, 0.f, 0.f);
        #pragma unroll
        for (int ss = 0; ss < NSPLIT; ss++) {
            float4 u = __ldcg(pt + (size_t)ss * 1024 + local4);
            v.x += u.x; v.y += u.y; v.z += u.z; v.w += u.w;
        }
        const int local = local4 * 4;
        const int m  = local >> 6;
        const int ng = tile * 64 + (local & 63);
        float4 b = __ldg((const float4*)&bias[ng]);
        v.x += b.x; v.y += b.y; v.z += b.z; v.w += b.w;
        if (bias2) {
            float4 b2 = __ldg((const float4*)&bias2[ng]);
            v.x += b2.x; v.y += b2.y; v.z += b2.z; v.w += b2.w;
        }
        float4 r;
        switch (mode) {
            case 0:
                r = make_float4(tanhf(v.x), tanhf(v.y), tanhf(v.z), tanhf(v.w));
                break;
            case 1:
                if (ng < Hd) r = make_float4(fmaxf(v.x,0.f), fmaxf(v.y,0.f), fmaxf(v.z,0.f), fmaxf(v.w,0.f));
                else         r = make_float4(1.f/(1.f+expf(-v.x)), 1.f/(1.f+expf(-v.y)),
                                             1.f/(1.f+expf(-v.z)), 1.f/(1.f+expf(-v.w)));
                break;
            case 2:
                if (ng < Hd) r = make_float4(tanhf(v.x), tanhf(v.y), tanhf(v.z), tanhf(v.w));
                else         r = make_float4(fmaxf(v.x,0.f), fmaxf(v.y,0.f), fmaxf(v.z,0.f), fmaxf(v.w,0.f));
                break;
            default: {
                float4 a1 = __ldcg((const float4*)&e1[(size_t)m * 2 * Hd + ng]);
                float4 a2 = __ldcg((const float4*)&e2[(size_t)m * 2 * Hd + ng]);
                r.x = g_c[2]*tanhf(v.x) + g_c[0]*a1.x + g_c[1]*a2.x;
                r.y = g_c[2]*tanhf(v.y) + g_c[0]*a1.y + g_c[1]*a2.y;
                r.z = g_c[2]*tanhf(v.z) + g_c[0]*a1.z + g_c[1]*a2.z;
                r.w = g_c[2]*tanhf(v.w) + g_c[0]*a1.w + g_c[1]*a2.w;
            }
        }
        __stcg((float4*)&out[(size_t)m * ldo + ng], r);
    }
}

// ---------- fp32 FFMA2 gemm (final GEMM only) ----------
template<int KPER>
__device__ __forceinline__ void gemm64_f32(
    const float* A, int lda, const float* Wp, int n0, int Nlim,
    float (*As)[TM][ASf], float (*Wsm)[TN][WSf], int tid, float vals[4][4])
{
    const int mr0 = tid >> 3, mr1 = mr0 + 32;
    const int kf  = (tid & 7) * 4;
    const float* arow0 = A + (size_t)mr0 * lda + kf;
    const float* arow1 = A + (size_t)mr1 * lda + kf;
    const bool wok0 = (n0 + mr0) < Nlim;
    const bool wok1 = (n0 + mr1) < Nlim;
    const float* wrow0 = Wp + (size_t)(n0 + mr0) * Hd + kf;
    const float* wrow1 = Wp + (size_t)(n0 + mr1) * Hd + kf;

    const int r  = tid >> 4;
    const int c  = tid & 15;
    const int mt = r * 4;

    unsigned long long acc[4][4];
    #pragma unroll
    for (int i = 0; i < 4; i++)
        #pragma unroll
        for (int j = 0; j < 4; j++) acc[i][j] = 0ull;

    const int nch = KPER / KCH;
    const float4 z4 = make_float4(0.f, 0.f, 0.f, 0.f);

    float4 va0 = __ldcg((const float4*)(arow0));
    float4 va1 = __ldcg((const float4*)(arow1));
    float4 vw0 = wok0 ? __ldg((const float4*)(wrow0)) : z4;
    float4 vw1 = wok1 ? __ldg((const float4*)(wrow1)) : z4;
    *(float4*)&As[0][mr0][kf] = va0;
    *(float4*)&As[0][mr1][kf] = va1;
    *(float2*)&Wsm[0][mr0][kf]     = make_float2(vw0.x, vw0.y);
    *(float2*)&Wsm[0][mr0][kf + 2] = make_float2(vw0.z, vw0.w);
    *(float2*)&Wsm[0][mr1][kf]     = make_float2(vw1.x, vw1.y);
    *(float2*)&Wsm[0][mr1][kf + 2] = make_float2(vw1.z, vw1.w);
    __syncthreads();

    for (int ch = 0; ch < nch; ch++) {
        const int b = ch & 1;
        const bool more = (ch + 1) < nch;
        if (more) {
            const int o = (ch + 1) * KCH;
            va0 = __ldcg((const float4*)(arow0 + o));
            va1 = __ldcg((const float4*)(arow1 + o));
            vw0 = wok0 ? __ldg((const float4*)(wrow0 + o)) : z4;
            vw1 = wok1 ? __ldg((const float4*)(wrow1 + o)) : z4;
        }
        #pragma unroll
        for (int k4 = 0; k4 < KCH / 4; k4++) {
            ulonglong2 a[4];
            #pragma unroll
            for (int i = 0; i < 4; i++)
                a[i] = *(const ulonglong2*)&As[b][mt + i][k4 * 4];
            #pragma unroll
            for (int j = 0; j < 4; j++) {
                const int n = c + 16 * j;
                unsigned long long wlo = *(const unsigned long long*)&Wsm[b][n][k4 * 4];
                unsigned long long whi = *(const unsigned long long*)&Wsm[b][n][k4 * 4 + 2];
                #pragma unroll
                for (int i = 0; i < 4; i++) {
                    acc[i][j] = ffma2(a[i].x, wlo, acc[i][j]);
                    acc[i][j] = ffma2(a[i].y, whi, acc[i][j]);
                }
            }
        }
        if (more) {
            const int nb = (ch + 1) & 1;
            *(float4*)&As[nb][mr0][kf] = va0;
            *(float4*)&As[nb][mr1][kf] = va1;
            *(float2*)&Wsm[nb][mr0][kf]     = make_float2(vw0.x, vw0.y);
            *(float2*)&Wsm[nb][mr0][kf + 2] = make_float2(vw0.z, vw0.w);
            *(float2*)&Wsm[nb][mr1][kf]     = make_float2(vw1.x, vw1.y);
            *(float2*)&Wsm[nb][mr1][kf + 2] = make_float2(vw1.z, vw1.w);
        }
        __syncthreads();
    }

    #pragma unroll
    for (int i = 0; i < 4; i++)
        #pragma unroll
        for (int j = 0; j < 4; j++) vals[i][j] = unpack_sum(acc[i][j]);
}

// ---------- persistent kernel ----------
__global__ void __launch_bounds__(256, 2) rnn_persistent(PArgs p) {
    extern __shared__ __align__(16) char smem[];

    const int bid = blockIdx.x;
    const int tid = threadIdx.x;

    if (bid == 0 && tid == 0) {
        const int rows[3] = {1, 3, 5};
        float wgt[3];
        for (int i = 0; i < 3; i++) {
            float acc = p.b_sum[rows[i]];
            for (int j = 0; j < 12; j++) acc += p.W_sum[rows[i] * 12 + j] * p.actions[j];
            wgt[i] = acc;
        }
        float mx = fmaxf(wgt[0], fmaxf(wgt[1], wgt[2]));
        float e0 = expf(wgt[0] - mx), e1 = expf(wgt[1] - mx), e2 = expf(wgt[2] - mx);
        float s = e0 + e1 + e2;
        g_c[0] = e0 / s; g_c[1] = e1 / s; g_c[2] = e2 / s;
    }

    unsigned bar = 0;

    // Pre-split recurrent weights (Ws then W0) into bf16 hi/lo, once per launch.
    {
        const int gtid = bid * 256 + tid;
        const int total4 = 7 * 1024 * 1024 / 4;
        const int ws4    = 6 * 1024 * 1024 / 4;
        for (int i = gtid; i < total4; i += GRID * 256) {
            float4 v = (i < ws4) ? __ldg((const float4*)p.Ws + i)
                                 : __ldg((const float4*)p.W0 + (i - ws4));
            split4(&g_Whi[(size_t)i * 4], &g_Wlo[(size_t)i * 4], v);
        }
    }
    grid_barrier(++bar);

    float* gh0 = g_h[0];
    float* gh1 = g_h[1];
    const int tile16 = bid >> 4, s16 = bid & 15;
    const int tile8  = bid >> 3, s8  = bid & 7;

    // Static per-CTA weight tile pointers for the 4 phases
    const size_t wo1 = (s16 < 8)
        ? (size_t)(tile16 * 64) * Hd + s16 * 128
        : (size_t)(6 * 1024 + tile16 * 64) * Hd + (s16 - 8) * 128;
    const size_t wo2 = (size_t)(1024 + tile8 * 64) * Hd + s8 * 128;
    const size_t wo3 = (size_t)(3 * 1024 + tile8 * 64) * Hd + s8 * 128;
    const size_t wo4 = (size_t)(5 * 1024 + tile16 * 64) * Hd + s16 * 64;

    // Prime phase-1 W (async; waited before first compute)
    stage_W_async<128>(g_Whi + wo1, g_Wlo + wo1, smem, tid);

    for (int t = 0; t < NSTEP; t++) {
        const float* hin  = (t == 0) ? p.h : ((t & 1) ? gh1 : gh0);
        float*       hout = ((t + 1) & 1) ? gh1 : gh0;

        // ---- phase 1: out1 = tanh(h @ Ws0^T + wv[idx] @ W0^T + bs0 + b0)  (nsplit=16) ----
        {
            float acc[4][4] = {};
            if (s16 < 8)
                stage_A<128, false>(hin, Hd, s16 * 128, nullptr, nullptr, smem, tid);
            else
                stage_A<128, true>(nullptr, 0, (s16 - 8) * 128, p.wv, p.bi + (t + 1), smem, tid);
            cp_wait0();
            __syncthreads();
            compute_mma<128>(smem, tid, acc);
            store_partial_mma(bid, tid, acc);
            __syncthreads();                       // all warps done reading sW
            stage_W_async<128>(g_Whi + wo2, g_Wlo + wo2, smem, tid);
        }
        group_sync(&g_tile_ctr[tile16], (unsigned)(t + 1) * 16u);
        group_reduce<16>(tile16, s16, tid, p.bs, p.b0, 0, g_out1, Hd, nullptr, nullptr);
        grid_barrier(++bar);

        // ---- phase 2: [out2|out3] = [relu|sigmoid](out1 @ [Ws1;Ws2]^T + b)  (nsplit=8) ----
        {
            float acc[4][4] = {};
            stage_A<128, false>(g_out1, Hd, s8 * 128, nullptr, nullptr, smem, tid);
            cp_wait0();
            __syncthreads();
            compute_mma<128>(smem, tid, acc);
            store_partial_mma(bid, tid, acc);
            __syncthreads();
            stage_W_async<128>(g_Whi + wo3, g_Wlo + wo3, smem, tid);
        }
        group_sync(&g_tile_ctr[16 + tile8], (unsigned)(t + 1) * 8u);
        group_reduce<8>(tile8, s8, tid, p.bs + Hd, nullptr, 1, g_out23, 2 * Hd, nullptr, nullptr);
        grid_barrier(++bar);

        // ---- phase 3: [out4|out5] = [tanh|relu](out3 @ [Ws3;Ws4]^T + b)  (nsplit=8) ----
        {
            float acc[4][4] = {};
            stage_A<128, false>(g_out23 + Hd, 2 * Hd, s8 * 128, nullptr, nullptr, smem, tid);
            cp_wait0();
            __syncthreads();
            compute_mma<128>(smem, tid, acc);
            store_partial_mma(bid, tid, acc);
            __syncthreads();
            stage_W_async<64>(g_Whi + wo4, g_Wlo + wo4, smem, tid);
        }
        group_sync(&g_tile_ctr[48 + tile8], (unsigned)(t + 1) * 8u);
        group_reduce<8>(tile8, s8, tid, p.bs + 3 * Hd, nullptr, 2, g_out45, 2 * Hd, nullptr, nullptr);
        grid_barrier(++bar);

        // ---- phase 4: h_new = c2*tanh(out5 @ Ws5^T + bs5) + c0*out2 + c1*out4  (nsplit=16) ----
        {
            float acc[4][4] = {};
            stage_A<64, false>(g_out45 + Hd, 2 * Hd, s16 * 64, nullptr, nullptr, smem, tid);
            cp_wait0();
            __syncthreads();
            compute_mma<64>(smem, tid, acc);
            store_partial_mma(bid, tid, acc);
            __syncthreads();
            stage_W_async<128>(g_Whi + wo1, g_Wlo + wo1, smem, tid);   // next t's phase 1
        }
        group_sync(&g_tile_ctr[80 + tile16], (unsigned)(t + 1) * 16u);
        group_reduce<16>(tile16, s16, tid, p.bs + 5 * Hd, nullptr, 3, hout, Hd, g_out23, g_out45);
        grid_barrier(++bar);
    }

    // drain the dangling phase-1 prefetch before reusing smem for the final GEMM
    cp_wait0();
    __syncthreads();

    // ---- final: logits = h_final @ W_out^T + b_out  [64, 50000]  (fp32, DRAM-bound) ----
    {
        float (*As)[TM][ASf]  = (float (*)[TM][ASf])smem;
        float (*Wsm)[TN][WSf] = (float (*)[TN][WSf])(smem + 2 * TM * ASf * 4);
        const float* hf = gh1;   // (126+1)&1 == 1
        const int ntiles = (Cc + TN - 1) / TN;
        const int mt = (tid >> 4) * 4;
        const int c  = tid & 15;
        float vals[4][4];
        for (int tile = bid; tile < ntiles; tile += GRID) {
            gemm64_f32<Hd>(hf, Hd, p.W_out, tile * 64, Cc, As, Wsm, tid, vals);
            #pragma unroll
            for (int i = 0; i < 4; i++)
                #pragma unroll
                for (int j = 0; j < 4; j++) {
                    const int ng = tile * 64 + c + 16 * j;
                    if (ng < Cc)
                        p.out[(size_t)(mt + i) * Cc + ng] = vals[i][j] + __ldg(&p.b_out[ng]);
                }
        }
    }

    // exit handshake: last CTA resets all sync state for the next graph replay
    __threadfence();
    __syncthreads();
    if (tid == 0) {
        unsigned prev = atomicAdd(&g_exit_cnt, 1u);
        if (prev == GRID - 1u) {
            for (int i = 0; i < 96; i++) g_tile_ctr[i] = 0u;
            g_exit_cnt = 0u;
            g_bar_cnt  = 0u;
            g_bar_gen  = 0u;
            __threadfence();
        }
    }
}

extern "C" void kernel_launch(void* const* d_in, const int* in_sizes, int n_in,
                              void* d_out, int out_size) {
    (void)in_sizes; (void)n_in; (void)out_size;
    PArgs p;
    p.wv      = (const float*)d_in[0];
    p.h       = (const float*)d_in[1];
    p.bi      = (const int*)  d_in[2];
    p.W0      = (const float*)d_in[3];
    p.b0      = (const float*)d_in[4];
    p.Ws      = (const float*)d_in[5];
    p.bs      = (const float*)d_in[6];
    p.W_out   = (const float*)d_in[7];
    p.b_out   = (const float*)d_in[8];
    p.W_sum   = (const float*)d_in[9];
    p.b_sum   = (const float*)d_in[10];
    p.actions = (const float*)d_in[11];
    p.out     = (float*)d_out;

    cudaFuncSetAttribute(rnn_persistent, cudaFuncAttributeMaxDynamicSharedMemorySize, SMEMB);
    cudaFuncSetAttribute(rnn_persistent, cudaFuncAttributePreferredSharedMemoryCarveout, 100);
    rnn_persistent<<<GRID, 256, SMEMB>>>(p);
}